// round 3
// baseline (speedup 1.0000x reference)
#include <cuda_runtime.h>
#include <cstdint>

// Problem dims
#define B     512
#define CIN   128
#define LIN   1024
#define KW    5
#define LOUT  1020          // 1024 - 4
#define TT    1020          // timesteps after reshape
#define D1    128           // LSTM1 input dim
#define H1    32
#define H2    16
#define H3    32
#define NG1   128           // 4*H1
#define NG2   64            // 4*H2
#define NG3   128           // 4*H3

#define XBSTR   (CIN*LIN)        // 131072
#define CBSTR   (CIN*LOUT)       // 130560 (also TT*D1)

// Scratch (device globals -- no runtime allocation allowed)
__device__ float g_conv[(size_t)B * CBSTR];   // conv output, [B][128][1020]; flat == seq [B][1020][128]
__device__ float g_xg  [(size_t)B * CBSTR];   // precomputed layer-1 input gates [B][1020][128]
__device__ float g_wT  [CIN * CIN * KW];      // conv weights as [ci][k][co]
__device__ float g_w1T [D1 * NG1];            // Wih1 transposed: [d][g]

__device__ __forceinline__ float sigf(float x) {
    return __fdividef(1.0f, 1.0f + __expf(-x));
}
__device__ __forceinline__ float tanhfast(float x) {
    x = fminf(15.0f, fmaxf(-15.0f, x));
    float e = __expf(2.0f * x);
    return __fdividef(e - 1.0f, e + 1.0f);
}

// ---------------- Kernel 0: weight transposes (tiny) ----------------
__global__ void prep_kernel(const float* __restrict__ conv_w, const float* __restrict__ Wih1) {
    int idx = blockIdx.x * 256 + threadIdx.x;
    if (idx < CIN * CIN * KW) {
        int co = idx / (CIN * KW);
        int rem = idx - co * (CIN * KW);
        int ci = rem / KW;
        int k  = rem - ci * KW;
        g_wT[ci * (CIN * KW / CIN * CIN) * 0 + ci * (KW * CIN) + k * CIN + co] = conv_w[idx];
    }
    if (idx < NG1 * D1) {
        int g = idx >> 7;     // /128
        int d = idx & 127;
        g_w1T[d * NG1 + g] = Wih1[idx];
    }
}

// ---------------- Kernel 1: conv1d as tiled GEMM ----------------
// Block: b = blockIdx.y, l-tile of 128 at l0 = blockIdx.x*128, all 128 co.
// 256 threads, each computes 8co x 8l. ci processed in 8 chunks of 16.
__global__ void conv_kernel(const float* __restrict__ x, const float* __restrict__ cb) {
    extern __shared__ float sm[];
    float* xs = sm;            // [16][132]  = 2112 floats
    float* ws = sm + 2112;     // [16][5][128] = 10240 floats

    int tid = threadIdx.x;
    int l0  = blockIdx.x * 128;
    int b   = blockIdx.y;
    int tl  = tid & 15;        // l group
    int tco = tid >> 4;        // co group

    float acc[8][8];
    #pragma unroll
    for (int c = 0; c < 8; ++c)
        #pragma unroll
        for (int li = 0; li < 8; ++li) acc[c][li] = 0.0f;

    const float* xb = x + (size_t)b * XBSTR;

    for (int ch = 0; ch < 8; ++ch) {
        int ci0 = ch * 16;
        for (int i = tid; i < 2112; i += 256) {
            int ci = i / 132;
            int j  = i - ci * 132;
            int l  = l0 + j;
            xs[i] = (l < LIN) ? xb[(ci0 + ci) * LIN + l] : 0.0f;
        }
        for (int i = tid; i < 10240; i += 256)
            ws[i] = g_wT[ci0 * (KW * CIN) + i];
        __syncthreads();

        #pragma unroll 2
        for (int ci = 0; ci < 16; ++ci) {
            float xv[12];
            const float* xr = &xs[ci * 132 + tl * 8];
            #pragma unroll
            for (int i = 0; i < 12; ++i) xv[i] = xr[i];
            #pragma unroll
            for (int k = 0; k < KW; ++k) {
                const float* wr = &ws[ci * (KW * CIN) + k * CIN + tco * 8];
                float wv[8];
                #pragma unroll
                for (int c = 0; c < 8; ++c) wv[c] = wr[c];
                #pragma unroll
                for (int c = 0; c < 8; ++c)
                    #pragma unroll
                    for (int li = 0; li < 8; ++li)
                        acc[c][li] = fmaf(wv[c], xv[li + k], acc[c][li]);
            }
        }
        __syncthreads();
    }

    #pragma unroll
    for (int c = 0; c < 8; ++c) {
        int co = tco * 8 + c;
        float bias = cb[co];
        float* dst = g_conv + (size_t)b * CBSTR + (size_t)co * LOUT + l0 + tl * 8;
        #pragma unroll
        for (int li = 0; li < 8; ++li) {
            int l = l0 + tl * 8 + li;
            if (l < LOUT) dst[li] = acc[c][li] + bias;
        }
    }
}

// ---------------- Kernel 2: xg1 = seq @ Wih1^T + (bih1 + bhh1) ----------------
// seq[b] as [1020,128] is the flat reinterpretation of g_conv[b].
// Block: b = blockIdx.y, t-tile 128 at t0. 256 threads, each 8t x 8g.
__global__ void xg_kernel(const float* __restrict__ bih1, const float* __restrict__ bhh1) {
    __shared__ float seqsT[32 * 129];   // [d][t] padded
    __shared__ float wts[32 * 128];     // [d][g]
    __shared__ float biasS[128];

    int tid = threadIdx.x;
    int t0  = blockIdx.x * 128;
    int b   = blockIdx.y;
    if (tid < 128) biasS[tid] = bih1[tid] + bhh1[tid];

    int tg = tid & 15;   // g group
    int ttid = tid >> 4; // t group

    float acc[8][8];
    #pragma unroll
    for (int i = 0; i < 8; ++i)
        #pragma unroll
        for (int j = 0; j < 8; ++j) acc[i][j] = 0.0f;

    const float* seqb = g_conv + (size_t)b * CBSTR;

    for (int ch = 0; ch < 4; ++ch) {
        int d0 = ch * 32;
        for (int i = tid; i < 4096; i += 256) {
            int t = i >> 5, d = i & 31;
            int tg_ = t0 + t;
            seqsT[d * 129 + t] = (tg_ < TT) ? seqb[(size_t)tg_ * D1 + d0 + d] : 0.0f;
        }
        for (int i = tid; i < 4096; i += 256)
            wts[i] = g_w1T[d0 * NG1 + i];
        __syncthreads();

        #pragma unroll 4
        for (int d = 0; d < 32; ++d) {
            float xv[8], wv[8];
            const float* sr = &seqsT[d * 129 + ttid * 8];
            #pragma unroll
            for (int i = 0; i < 8; ++i) xv[i] = sr[i];
            const float* wr = &wts[d * NG1 + tg * 8];
            #pragma unroll
            for (int j = 0; j < 8; ++j) wv[j] = wr[j];
            #pragma unroll
            for (int i = 0; i < 8; ++i)
                #pragma unroll
                for (int j = 0; j < 8; ++j)
                    acc[i][j] = fmaf(xv[i], wv[j], acc[i][j]);
        }
        __syncthreads();
    }

    #pragma unroll
    for (int i = 0; i < 8; ++i) {
        int t = t0 + ttid * 8 + i;
        if (t < TT) {
            float* dst = g_xg + (size_t)b * CBSTR + (size_t)t * D1 + tg * 8;
            #pragma unroll
            for (int j = 0; j < 8; ++j) dst[j] = acc[i][j] + biasS[tg * 8 + j];
        }
    }
}

// ---------------- Kernel 3: 3-layer LSTM recurrence ----------------
// One CTA per batch element, 128 threads (= one gate each for layers 1/3).
__global__ void lstm_kernel(
    const float* __restrict__ Whh1,
    const float* __restrict__ Wih2, const float* __restrict__ Whh2,
    const float* __restrict__ bih2, const float* __restrict__ bhh2,
    const float* __restrict__ Wih3, const float* __restrict__ Whh3,
    const float* __restrict__ bih3, const float* __restrict__ bhh3,
    float* __restrict__ out)
{
    extern __shared__ float sm[];
    float* W1t  = sm;                 // [32][128]  Whh1^T
    float* Wi2t = W1t  + 32 * 128;    // [32][64]   Wih2^T
    float* Wh2t = Wi2t + 32 * 64;     // [16][64]   Whh2^T
    float* Wi3t = Wh2t + 16 * 64;     // [16][128]  Wih3^T
    float* Wh3t = Wi3t + 16 * 128;    // [32][128]  Whh3^T
    float* b2s  = Wh3t + 32 * 128;    // [64]
    float* b3s  = b2s  + 64;          // [128]
    float* h1s  = b3s  + 128;         // [32]
    float* c1s  = h1s  + 32;
    float* h2s  = c1s  + 32;          // [16]
    float* c2s  = h2s  + 16;
    float* h3s  = c2s  + 16;          // [32]
    float* c3s  = h3s  + 32;
    float* gs   = c3s  + 32;          // [128] gate buffer

    int g = threadIdx.x;
    int b = blockIdx.x;

    for (int i = g; i < 4096; i += 128) { int j = i >> 7, q = i & 127; W1t[i]  = Whh1[q * 32 + j]; }
    for (int i = g; i < 2048; i += 128) { int j = i >> 6, q = i & 63;  Wi2t[i] = Wih2[q * 32 + j]; }
    for (int i = g; i < 1024; i += 128) { int j = i >> 6, q = i & 63;  Wh2t[i] = Whh2[q * 16 + j]; }
    for (int i = g; i < 2048; i += 128) { int j = i >> 7, q = i & 127; Wi3t[i] = Wih3[q * 16 + j]; }
    for (int i = g; i < 4096; i += 128) { int j = i >> 7, q = i & 127; Wh3t[i] = Whh3[q * 32 + j]; }
    if (g < 64) b2s[g] = bih2[g] + bhh2[g];
    b3s[g] = bih3[g] + bhh3[g];
    if (g < 32) { h1s[g] = 0.f; c1s[g] = 0.f; h3s[g] = 0.f; c3s[g] = 0.f; }
    if (g < 16) { h2s[g] = 0.f; c2s[g] = 0.f; }
    __syncthreads();

    float bias2 = (g < 64) ? b2s[g] : 0.0f;
    float bias3 = b3s[g];

    const float* xgp = g_xg + (size_t)b * CBSTR + g;
    float xnext = xgp[0];

    for (int t = 0; t < TT; ++t) {
        float xcur = xnext;
        if (t < TT - 1) xnext = xgp[(t + 1) * D1];

        // --- layer 1 gates (128 threads, one gate each) ---
        {
            float a0 = xcur, a1 = 0.f, a2 = 0.f, a3 = 0.f;
            #pragma unroll
            for (int j = 0; j < 32; j += 4) {
                a0 = fmaf(h1s[j    ], W1t[(j    ) * 128 + g], a0);
                a1 = fmaf(h1s[j + 1], W1t[(j + 1) * 128 + g], a1);
                a2 = fmaf(h1s[j + 2], W1t[(j + 2) * 128 + g], a2);
                a3 = fmaf(h1s[j + 3], W1t[(j + 3) * 128 + g], a3);
            }
            gs[g] = (a0 + a1) + (a2 + a3);
        }
        __syncthreads();
        if (g < 32) {
            float c = sigf(gs[32 + g]) * c1s[g] + sigf(gs[g]) * tanhfast(gs[64 + g]);
            c1s[g] = c;
            h1s[g] = sigf(gs[96 + g]) * tanhfast(c);
        }
        __syncthreads();

        // --- layer 2 gates (64 threads) ---
        if (g < 64) {
            float a0 = bias2, a1 = 0.f, a2 = 0.f, a3 = 0.f;
            #pragma unroll
            for (int j = 0; j < 32; j += 4) {
                a0 = fmaf(h1s[j    ], Wi2t[(j    ) * 64 + g], a0);
                a1 = fmaf(h1s[j + 1], Wi2t[(j + 1) * 64 + g], a1);
                a2 = fmaf(h1s[j + 2], Wi2t[(j + 2) * 64 + g], a2);
                a3 = fmaf(h1s[j + 3], Wi2t[(j + 3) * 64 + g], a3);
            }
            #pragma unroll
            for (int j = 0; j < 16; j += 4) {
                a0 = fmaf(h2s[j    ], Wh2t[(j    ) * 64 + g], a0);
                a1 = fmaf(h2s[j + 1], Wh2t[(j + 1) * 64 + g], a1);
                a2 = fmaf(h2s[j + 2], Wh2t[(j + 2) * 64 + g], a2);
                a3 = fmaf(h2s[j + 3], Wh2t[(j + 3) * 64 + g], a3);
            }
            gs[g] = (a0 + a1) + (a2 + a3);
        }
        __syncthreads();
        if (g < 16) {
            float c = sigf(gs[16 + g]) * c2s[g] + sigf(gs[g]) * tanhfast(gs[32 + g]);
            c2s[g] = c;
            h2s[g] = sigf(gs[48 + g]) * tanhfast(c);
        }
        __syncthreads();

        // --- layer 3 gates (128 threads) ---
        {
            float a0 = bias3, a1 = 0.f, a2 = 0.f, a3 = 0.f;
            #pragma unroll
            for (int j = 0; j < 16; j += 4) {
                a0 = fmaf(h2s[j    ], Wi3t[(j    ) * 128 + g], a0);
                a1 = fmaf(h2s[j + 1], Wi3t[(j + 1) * 128 + g], a1);
                a2 = fmaf(h2s[j + 2], Wi3t[(j + 2) * 128 + g], a2);
                a3 = fmaf(h2s[j + 3], Wi3t[(j + 3) * 128 + g], a3);
            }
            #pragma unroll
            for (int j = 0; j < 32; j += 4) {
                a0 = fmaf(h3s[j    ], Wh3t[(j    ) * 128 + g], a0);
                a1 = fmaf(h3s[j + 1], Wh3t[(j + 1) * 128 + g], a1);
                a2 = fmaf(h3s[j + 2], Wh3t[(j + 2) * 128 + g], a2);
                a3 = fmaf(h3s[j + 3], Wh3t[(j + 3) * 128 + g], a3);
            }
            gs[g] = (a0 + a1) + (a2 + a3);
        }
        __syncthreads();
        if (g < 32) {
            float c = sigf(gs[32 + g]) * c3s[g] + sigf(gs[g]) * tanhfast(gs[64 + g]);
            c3s[g] = c;
            h3s[g] = sigf(gs[96 + g]) * tanhfast(c);
        }
        __syncthreads();
    }

    if (g < 32) out[b * 32 + g] = h3s[g];
}

// ---------------- launch ----------------
extern "C" void kernel_launch(void* const* d_in, const int* in_sizes, int n_in,
                              void* d_out, int out_size) {
    const float* x      = (const float*)d_in[0];
    const float* conv_w = (const float*)d_in[1];
    const float* conv_b = (const float*)d_in[2];
    const float* Wih1   = (const float*)d_in[3];
    const float* Whh1   = (const float*)d_in[4];
    const float* bih1   = (const float*)d_in[5];
    const float* bhh1   = (const float*)d_in[6];
    const float* Wih2   = (const float*)d_in[7];
    const float* Whh2   = (const float*)d_in[8];
    const float* bih2   = (const float*)d_in[9];
    const float* bhh2   = (const float*)d_in[10];
    const float* Wih3   = (const float*)d_in[11];
    const float* Whh3   = (const float*)d_in[12];
    const float* bih3   = (const float*)d_in[13];
    const float* bhh3   = (const float*)d_in[14];
    float* out = (float*)d_out;

    const int conv_smem = (2112 + 10240) * 4;          // 49408 B
    const int lstm_smem = (4096 + 2048 + 1024 + 2048 + 4096 + 64 + 128 + 160 + 128) * 4; // 55168 B
    cudaFuncSetAttribute(conv_kernel, cudaFuncAttributeMaxDynamicSharedMemorySize, conv_smem);
    cudaFuncSetAttribute(lstm_kernel, cudaFuncAttributeMaxDynamicSharedMemorySize, lstm_smem);

    prep_kernel<<<(CIN * CIN * KW + 255) / 256, 256>>>(conv_w, Wih1);
    conv_kernel<<<dim3(8, B), 256, conv_smem>>>(x, conv_b);
    xg_kernel<<<dim3(8, B), 256>>>(bih1, bhh1);
    lstm_kernel<<<B, 128, lstm_smem>>>(Whh1, Wih2, Whh2, bih2, bhh2,
                                       Wih3, Whh3, bih3, bhh3, out);
}

// round 4
// speedup vs baseline: 1.0917x; 1.0917x over previous
#include <cuda_runtime.h>
#include <cuda_bf16.h>
#include <cstdint>

// Problem dims
#define B     512
#define CIN   128
#define LIN   1024
#define KW    5
#define LOUT  1020
#define TT    1020
#define D1    128
#define H1    32
#define H2    16
#define H3    32

#define XBSTR   (CIN*LIN)        // 131072
#define CBSTR   (CIN*LOUT)       // 130560 == TT*D1

// ---- scratch (device globals; no runtime allocation allowed) ----
__device__ __nv_bfloat16 g_seq_hi[(size_t)B * CBSTR];  // conv out (== seq) bf16 hi
__device__ __nv_bfloat16 g_seq_lo[(size_t)B * CBSTR];  // residual lo
__device__ float         g_xg   [(size_t)B * CBSTR];   // layer-1 input gates fp32
__device__ unsigned      g_wp_hi[128 * 320];           // conv W packed pairs [co][kidx/2], kidx=k*128+ci
__device__ unsigned      g_wp_lo[128 * 320];
__device__ unsigned      g_w1p_hi[128 * 64];           // Wih1 packed pairs [gate][d/2]
__device__ unsigned      g_w1p_lo[128 * 64];

__device__ __forceinline__ float sigf(float x) {
    return __fdividef(1.0f, 1.0f + __expf(-x));
}
__device__ __forceinline__ float tanhfast(float x) {
    x = fminf(15.0f, fmaxf(-15.0f, x));
    float e = __expf(2.0f * x);
    return __fdividef(e - 1.0f, e + 1.0f);
}

__device__ __forceinline__ void split2(float v0, float v1, unsigned &uh, unsigned &ul) {
    __nv_bfloat16 h0 = __float2bfloat16_rn(v0);
    __nv_bfloat16 h1 = __float2bfloat16_rn(v1);
    float r0 = v0 - __bfloat162float(h0);
    float r1 = v1 - __bfloat162float(h1);
    __nv_bfloat162 ph; ph.x = h0; ph.y = h1;
    __nv_bfloat162 pl; pl.x = __float2bfloat16_rn(r0); pl.y = __float2bfloat16_rn(r1);
    uh = *(unsigned*)&ph;
    ul = *(unsigned*)&pl;
}

#define MMA_BF16(d, a0,a1,a2,a3, b0,b1)                                     \
    asm volatile("mma.sync.aligned.m16n8k16.row.col.f32.bf16.bf16.f32 "     \
        "{%0,%1,%2,%3},{%4,%5,%6,%7},{%8,%9},{%0,%1,%2,%3};"                \
        : "+f"(d[0]), "+f"(d[1]), "+f"(d[2]), "+f"(d[3])                    \
        : "r"(a0), "r"(a1), "r"(a2), "r"(a3), "r"(b0), "r"(b1))

// ---------------- Kernel 0: pack weights into mma fragment order ----------------
__global__ void prep_kernel(const float* __restrict__ conv_w, const float* __restrict__ Wih1) {
    int idx = blockIdx.x * 256 + threadIdx.x;
    if (idx < 128 * 320) {
        int co = idx / 320, j = idx % 320;
        int kidx = 2 * j;
        int k = kidx >> 7, ci = kidx & 127;
        float v0 = conv_w[(co * 128 + ci) * 5 + k];
        float v1 = conv_w[(co * 128 + ci + 1) * 5 + k];
        unsigned uh, ul; split2(v0, v1, uh, ul);
        g_wp_hi[idx] = uh; g_wp_lo[idx] = ul;
    }
    if (idx < 128 * 64) {
        int g = idx / 64, j = idx % 64;
        float v0 = Wih1[g * 128 + 2 * j];
        float v1 = Wih1[g * 128 + 2 * j + 1];
        unsigned uh, ul; split2(v0, v1, uh, ul);
        g_w1p_hi[idx] = uh; g_w1p_lo[idx] = ul;
    }
}

// ---------------- Kernel 1: conv1d via bf16-split tensor-core GEMM ----------------
// C[co=128][l-tile=128] = sum_{k,ci} W[co][(k,ci)] * x[ci][l+k]
// grid(8, B), 256 threads = 8 warps (wm=warp&3 over co, wn=warp>>2 over l).
// smem: XsT[j=l_local+k][ci] bf16 hi+lo, row stride 136 bf16 (68 uints).
__global__ void __launch_bounds__(256) conv_mma_kernel(const float* __restrict__ x,
                                                       const float* __restrict__ cb) {
    extern __shared__ unsigned sm[];
    unsigned* sH = sm;               // 136*68 uints
    unsigned* sL = sm + 136 * 68;

    int tid  = threadIdx.x;
    int warp = tid >> 5, lane = tid & 31;
    int gid  = lane >> 2, tig = lane & 3;
    int wm   = warp & 3;     // co tile (4 x 32)
    int wn   = warp >> 2;    // l tile  (2 x 64)
    int l0   = blockIdx.x * 128;
    int b    = blockIdx.y;

    // stage transposed x tile, split to bf16 hi/lo
    const float* xb = x + (size_t)b * XBSTR;
    __nv_bfloat16* sHb = (__nv_bfloat16*)sH;
    __nv_bfloat16* sLb = (__nv_bfloat16*)sL;
    for (int ci = warp; ci < 128; ci += 8) {
        for (int j = lane; j < 136; j += 32) {
            int l = l0 + j;
            float v = (l < LIN) ? xb[ci * LIN + l] : 0.0f;
            __nv_bfloat16 h = __float2bfloat16_rn(v);
            float r = v - __bfloat162float(h);
            sHb[j * 136 + ci] = h;
            sLb[j * 136 + ci] = __float2bfloat16_rn(r);
        }
    }
    __syncthreads();

    float acc[2][8][4];
    #pragma unroll
    for (int mi = 0; mi < 2; ++mi)
        #pragma unroll
        for (int ni = 0; ni < 8; ++ni)
            #pragma unroll
            for (int q = 0; q < 4; ++q) acc[mi][ni][q] = 0.0f;

    int co_base0 = wm * 32 + gid;

    for (int k5 = 0; k5 < 5; ++k5) {
        #pragma unroll
        for (int cc = 0; cc < 8; ++cc) {
            int base = k5 * 64 + cc * 8 + tig;
            unsigned ah[2][4], al[2][4];
            #pragma unroll
            for (int mi = 0; mi < 2; ++mi) {
                int co = co_base0 + mi * 16;
                ah[mi][0] = g_wp_hi[co * 320 + base];
                ah[mi][1] = g_wp_hi[(co + 8) * 320 + base];
                ah[mi][2] = g_wp_hi[co * 320 + base + 4];
                ah[mi][3] = g_wp_hi[(co + 8) * 320 + base + 4];
                al[mi][0] = g_wp_lo[co * 320 + base];
                al[mi][1] = g_wp_lo[(co + 8) * 320 + base];
                al[mi][2] = g_wp_lo[co * 320 + base + 4];
                al[mi][3] = g_wp_lo[(co + 8) * 320 + base + 4];
            }
            #pragma unroll
            for (int ni = 0; ni < 8; ++ni) {
                int r = (wn * 64 + ni * 8 + gid + k5) * 68 + cc * 8 + tig;
                unsigned bh0 = sH[r], bh1 = sH[r + 4];
                unsigned bl0 = sL[r], bl1 = sL[r + 4];
                #pragma unroll
                for (int mi = 0; mi < 2; ++mi) {
                    MMA_BF16(acc[mi][ni], ah[mi][0], ah[mi][1], ah[mi][2], ah[mi][3], bh0, bh1);
                    MMA_BF16(acc[mi][ni], ah[mi][0], ah[mi][1], ah[mi][2], ah[mi][3], bl0, bl1);
                    MMA_BF16(acc[mi][ni], al[mi][0], al[mi][1], al[mi][2], al[mi][3], bh0, bh1);
                }
            }
        }
    }

    // epilogue: +bias, split to bf16 hi/lo, write to g_seq (flat conv layout)
    __nv_bfloat16* oh = g_seq_hi + (size_t)b * CBSTR;
    __nv_bfloat16* ol = g_seq_lo + (size_t)b * CBSTR;
    #pragma unroll
    for (int mi = 0; mi < 2; ++mi) {
        int coA = co_base0 + mi * 16;
        int coB = coA + 8;
        float biasA = cb[coA], biasB = cb[coB];
        #pragma unroll
        for (int ni = 0; ni < 8; ++ni) {
            int lloc = wn * 64 + ni * 8 + tig * 2;
            int lg = l0 + lloc;
            if (lg < LOUT) {  // lg even, so lg+1 <= 1019 safe
                unsigned uh, ul;
                int fA = coA * LOUT + lg;
                split2(acc[mi][ni][0] + biasA, acc[mi][ni][1] + biasA, uh, ul);
                *(unsigned*)(oh + fA) = uh; *(unsigned*)(ol + fA) = ul;
                int fB = coB * LOUT + lg;
                split2(acc[mi][ni][2] + biasB, acc[mi][ni][3] + biasB, uh, ul);
                *(unsigned*)(oh + fB) = uh; *(unsigned*)(ol + fB) = ul;
            }
        }
    }
}

// ---------------- Kernel 2: xg = seq @ Wih1^T + bias via bf16-split mma ----------------
// grid(8, B), 256 threads. M = t (128 tile), N = gate (128), K = d (128).
__global__ void __launch_bounds__(256) xg_mma_kernel(const float* __restrict__ bih1,
                                                     const float* __restrict__ bhh1) {
    extern __shared__ unsigned sm[];
    unsigned* sH = sm;               // 128 rows * 68 uints
    unsigned* sL = sm + 128 * 68;

    int tid  = threadIdx.x;
    int warp = tid >> 5, lane = tid & 31;
    int gid  = lane >> 2, tig = lane & 3;
    int wm   = warp & 3;     // t tile (4 x 32)
    int wn   = warp >> 2;    // gate tile (2 x 64)
    int t0   = blockIdx.x * 128;
    int b    = blockIdx.y;

    // stage seq tile rows (already bf16 hi/lo, contiguous) — coalesced
    const __nv_bfloat16* shd = g_seq_hi + (size_t)b * CBSTR;
    const __nv_bfloat16* sld = g_seq_lo + (size_t)b * CBSTR;
    for (int row = warp; row < 128; row += 8) {
        int t = t0 + row;
        int d = lane * 4;
        uint2 vh = make_uint2(0u, 0u), vl = make_uint2(0u, 0u);
        if (t < TT) {
            vh = *(const uint2*)(shd + (size_t)t * D1 + d);
            vl = *(const uint2*)(sld + (size_t)t * D1 + d);
        }
        *(uint2*)((__nv_bfloat16*)sH + row * 136 + d) = vh;
        *(uint2*)((__nv_bfloat16*)sL + row * 136 + d) = vl;
    }
    __syncthreads();

    float acc[2][8][4];
    #pragma unroll
    for (int mi = 0; mi < 2; ++mi)
        #pragma unroll
        for (int ni = 0; ni < 8; ++ni)
            #pragma unroll
            for (int q = 0; q < 4; ++q) acc[mi][ni][q] = 0.0f;

    #pragma unroll
    for (int kk = 0; kk < 8; ++kk) {
        unsigned ah[2][4], al[2][4];
        #pragma unroll
        for (int mi = 0; mi < 2; ++mi) {
            int r = (wm * 32 + mi * 16 + gid) * 68 + kk * 8 + tig;
            ah[mi][0] = sH[r];           ah[mi][1] = sH[r + 8 * 68];
            ah[mi][2] = sH[r + 4];       ah[mi][3] = sH[r + 8 * 68 + 4];
            al[mi][0] = sL[r];           al[mi][1] = sL[r + 8 * 68];
            al[mi][2] = sL[r + 4];       al[mi][3] = sL[r + 8 * 68 + 4];
        }
        #pragma unroll
        for (int ni = 0; ni < 8; ++ni) {
            int gg = wn * 64 + ni * 8 + gid;
            unsigned bh0 = g_w1p_hi[gg * 64 + kk * 8 + tig];
            unsigned bh1 = g_w1p_hi[gg * 64 + kk * 8 + tig + 4];
            unsigned bl0 = g_w1p_lo[gg * 64 + kk * 8 + tig];
            unsigned bl1 = g_w1p_lo[gg * 64 + kk * 8 + tig + 4];
            #pragma unroll
            for (int mi = 0; mi < 2; ++mi) {
                MMA_BF16(acc[mi][ni], ah[mi][0], ah[mi][1], ah[mi][2], ah[mi][3], bh0, bh1);
                MMA_BF16(acc[mi][ni], ah[mi][0], ah[mi][1], ah[mi][2], ah[mi][3], bl0, bl1);
                MMA_BF16(acc[mi][ni], al[mi][0], al[mi][1], al[mi][2], al[mi][3], bh0, bh1);
            }
        }
    }

    float* xgb = g_xg + (size_t)b * CBSTR;
    #pragma unroll
    for (int ni = 0; ni < 8; ++ni) {
        int gcol = wn * 64 + ni * 8 + tig * 2;
        float bi0 = bih1[gcol] + bhh1[gcol];
        float bi1 = bih1[gcol + 1] + bhh1[gcol + 1];
        #pragma unroll
        for (int mi = 0; mi < 2; ++mi) {
            int tA = t0 + wm * 32 + mi * 16 + gid;
            if (tA < TT) {
                float2 v = make_float2(acc[mi][ni][0] + bi0, acc[mi][ni][1] + bi1);
                *(float2*)(xgb + (size_t)tA * D1 + gcol) = v;
            }
            int tB = tA + 8;
            if (tB < TT) {
                float2 v = make_float2(acc[mi][ni][2] + bi0, acc[mi][ni][3] + bi1);
                *(float2*)(xgb + (size_t)tB * D1 + gcol) = v;
            }
        }
    }
}

// ---------------- Kernel 3: 3-layer LSTM recurrence ----------------
// One CTA per batch, 128 threads. Weights in REGISTERS (rows are contiguous
// in the PyTorch layout), h-vectors broadcast via float4 LDS from uniform addr.
__global__ void __launch_bounds__(128) lstm_kernel(
    const float* __restrict__ Whh1,
    const float* __restrict__ Wih2, const float* __restrict__ Whh2,
    const float* __restrict__ bih2, const float* __restrict__ bhh2,
    const float* __restrict__ Wih3, const float* __restrict__ Whh3,
    const float* __restrict__ bih3, const float* __restrict__ bhh3,
    float* __restrict__ out)
{
    __shared__ float h1s[32], h2s[16], h3s[32], gs[128];

    int g = threadIdx.x;
    int b = blockIdx.x;

    // register weights: row g of each matrix
    float4 w1[8];                       // Whh1[g][0..31]
    #pragma unroll
    for (int i = 0; i < 8; ++i) w1[i] = *(const float4*)(Whh1 + g * 32 + i * 4);
    float4 w2i[8], w2h[4];              // threads < 64
    if (g < 64) {
        #pragma unroll
        for (int i = 0; i < 8; ++i) w2i[i] = *(const float4*)(Wih2 + g * 32 + i * 4);
        #pragma unroll
        for (int i = 0; i < 4; ++i) w2h[i] = *(const float4*)(Whh2 + g * 16 + i * 4);
    }
    float4 w3i[4], w3h[8];
    #pragma unroll
    for (int i = 0; i < 4; ++i) w3i[i] = *(const float4*)(Wih3 + g * 16 + i * 4);
    #pragma unroll
    for (int i = 0; i < 8; ++i) w3h[i] = *(const float4*)(Whh3 + g * 32 + i * 4);

    float bias2 = (g < 64) ? (bih2[g] + bhh2[g]) : 0.0f;
    float bias3 = bih3[g] + bhh3[g];

    if (g < 32) { h1s[g] = 0.f; h3s[g] = 0.f; }
    if (g < 16) { h2s[g] = 0.f; }
    float c1 = 0.f, c2 = 0.f, c3 = 0.f;
    __syncthreads();

    const float* xgp = g_xg + (size_t)b * CBSTR + g;
    float xnext = xgp[0];

    for (int t = 0; t < TT; ++t) {
        float xcur = xnext;
        if (t < TT - 1) xnext = xgp[(size_t)(t + 1) * D1];

        // layer 1 gates
        {
            float a0 = xcur, a1 = 0.f, a2 = 0.f, a3 = 0.f;
            #pragma unroll
            for (int i = 0; i < 8; ++i) {
                float4 h = ((const float4*)h1s)[i];
                a0 = fmaf(h.x, w1[i].x, a0);
                a1 = fmaf(h.y, w1[i].y, a1);
                a2 = fmaf(h.z, w1[i].z, a2);
                a3 = fmaf(h.w, w1[i].w, a3);
            }
            gs[g] = (a0 + a1) + (a2 + a3);
        }
        __syncthreads();
        if (g < 32) {
            c1 = sigf(gs[32 + g]) * c1 + sigf(gs[g]) * tanhfast(gs[64 + g]);
            h1s[g] = sigf(gs[96 + g]) * tanhfast(c1);
        }
        __syncthreads();

        // layer 2 gates
        if (g < 64) {
            float a0 = bias2, a1 = 0.f, a2 = 0.f, a3 = 0.f;
            #pragma unroll
            for (int i = 0; i < 8; ++i) {
                float4 h = ((const float4*)h1s)[i];
                a0 = fmaf(h.x, w2i[i].x, a0);
                a1 = fmaf(h.y, w2i[i].y, a1);
                a2 = fmaf(h.z, w2i[i].z, a2);
                a3 = fmaf(h.w, w2i[i].w, a3);
            }
            #pragma unroll
            for (int i = 0; i < 4; ++i) {
                float4 h = ((const float4*)h2s)[i];
                a0 = fmaf(h.x, w2h[i].x, a0);
                a1 = fmaf(h.y, w2h[i].y, a1);
                a2 = fmaf(h.z, w2h[i].z, a2);
                a3 = fmaf(h.w, w2h[i].w, a3);
            }
            gs[g] = (a0 + a1) + (a2 + a3);
        }
        __syncthreads();
        if (g < 16) {
            c2 = sigf(gs[16 + g]) * c2 + sigf(gs[g]) * tanhfast(gs[32 + g]);
            h2s[g] = sigf(gs[48 + g]) * tanhfast(c2);
        }
        __syncthreads();

        // layer 3 gates
        {
            float a0 = bias3, a1 = 0.f, a2 = 0.f, a3 = 0.f;
            #pragma unroll
            for (int i = 0; i < 4; ++i) {
                float4 h = ((const float4*)h2s)[i];
                a0 = fmaf(h.x, w3i[i].x, a0);
                a1 = fmaf(h.y, w3i[i].y, a1);
                a2 = fmaf(h.z, w3i[i].z, a2);
                a3 = fmaf(h.w, w3i[i].w, a3);
            }
            #pragma unroll
            for (int i = 0; i < 8; ++i) {
                float4 h = ((const float4*)h3s)[i];
                a0 = fmaf(h.x, w3h[i].x, a0);
                a1 = fmaf(h.y, w3h[i].y, a1);
                a2 = fmaf(h.z, w3h[i].z, a2);
                a3 = fmaf(h.w, w3h[i].w, a3);
            }
            gs[g] = (a0 + a1) + (a2 + a3);
        }
        __syncthreads();
        if (g < 32) {
            c3 = sigf(gs[32 + g]) * c3 + sigf(gs[g]) * tanhfast(gs[64 + g]);
            h3s[g] = sigf(gs[96 + g]) * tanhfast(c3);
        }
        __syncthreads();
    }

    if (g < 32) out[b * 32 + g] = h3s[g];
}

// ---------------- launch ----------------
extern "C" void kernel_launch(void* const* d_in, const int* in_sizes, int n_in,
                              void* d_out, int out_size) {
    const float* x      = (const float*)d_in[0];
    const float* conv_w = (const float*)d_in[1];
    const float* conv_b = (const float*)d_in[2];
    const float* Wih1   = (const float*)d_in[3];
    const float* Whh1   = (const float*)d_in[4];
    const float* bih1   = (const float*)d_in[5];
    const float* bhh1   = (const float*)d_in[6];
    const float* Wih2   = (const float*)d_in[7];
    const float* Whh2   = (const float*)d_in[8];
    const float* bih2   = (const float*)d_in[9];
    const float* bhh2   = (const float*)d_in[10];
    const float* Wih3   = (const float*)d_in[11];
    const float* Whh3   = (const float*)d_in[12];
    const float* bih3   = (const float*)d_in[13];
    const float* bhh3   = (const float*)d_in[14];
    float* out = (float*)d_out;

    const int conv_smem = 2 * 136 * 68 * 4;   // 73984 B
    const int xg_smem   = 2 * 128 * 68 * 4;   // 69632 B
    cudaFuncSetAttribute(conv_mma_kernel, cudaFuncAttributeMaxDynamicSharedMemorySize, conv_smem);
    cudaFuncSetAttribute(xg_mma_kernel,   cudaFuncAttributeMaxDynamicSharedMemorySize, xg_smem);

    prep_kernel<<<160, 256>>>(conv_w, Wih1);
    conv_mma_kernel<<<dim3(8, B), 256, conv_smem>>>(x, conv_b);
    xg_mma_kernel<<<dim3(8, B), 256, xg_smem>>>(bih1, bhh1);
    lstm_kernel<<<B, 128>>>(Whh1, Wih2, Whh2, bih2, bhh2,
                            Wih3, Whh3, bih3, bhh3, out);
}

// round 5
// speedup vs baseline: 1.2933x; 1.1847x over previous
#include <cuda_runtime.h>
#include <cuda_bf16.h>
#include <cstdint>

// Problem dims
#define B     512
#define CIN   128
#define LIN   1024
#define KW    5
#define LOUT  1020
#define TT    1020
#define D1    128
#define H1    32
#define H2    16
#define H3    32

#define XBSTR   (CIN*LIN)        // 131072
#define CBSTR   (CIN*LOUT)       // 130560 == TT*D1

// ---- scratch (device globals; no runtime allocation allowed) ----
__device__ __nv_bfloat16 g_seq_hi[(size_t)B * CBSTR];
__device__ __nv_bfloat16 g_seq_lo[(size_t)B * CBSTR];
__device__ float         g_xg   [(size_t)B * CBSTR];
__device__ unsigned      g_wp_hi[128 * 320];   // conv W pairs [co][kidx/2], kidx=k*128+ci
__device__ unsigned      g_wp_lo[128 * 320];
__device__ unsigned      g_w1p_hi[128 * 64];   // Wih1 pairs [gate][d/2]
__device__ unsigned      g_w1p_lo[128 * 64];

__device__ __forceinline__ float sigf(float x) {
    return __fdividef(1.0f, 1.0f + __expf(-x));
}
__device__ __forceinline__ float tanhfast(float x) {
    x = fminf(15.0f, fmaxf(-15.0f, x));
    float e = __expf(2.0f * x);
    return __fdividef(e - 1.0f, e + 1.0f);
}

__device__ __forceinline__ void split2(float v0, float v1, unsigned &uh, unsigned &ul) {
    __nv_bfloat16 h0 = __float2bfloat16_rn(v0);
    __nv_bfloat16 h1 = __float2bfloat16_rn(v1);
    float r0 = v0 - __bfloat162float(h0);
    float r1 = v1 - __bfloat162float(h1);
    __nv_bfloat162 ph; ph.x = h0; ph.y = h1;
    __nv_bfloat162 pl; pl.x = __float2bfloat16_rn(r0); pl.y = __float2bfloat16_rn(r1);
    uh = *(unsigned*)&ph;
    ul = *(unsigned*)&pl;
}

#define MMA_BF16(d, a0,a1,a2,a3, b0,b1)                                     \
    asm volatile("mma.sync.aligned.m16n8k16.row.col.f32.bf16.bf16.f32 "     \
        "{%0,%1,%2,%3},{%4,%5,%6,%7},{%8,%9},{%0,%1,%2,%3};"                \
        : "+f"(d[0]), "+f"(d[1]), "+f"(d[2]), "+f"(d[3])                    \
        : "r"(a0), "r"(a1), "r"(a2), "r"(a3), "r"(b0), "r"(b1))

// ---------------- Kernel 0: pack weights into mma fragment order ----------------
__global__ void prep_kernel(const float* __restrict__ conv_w, const float* __restrict__ Wih1) {
    int idx = blockIdx.x * 256 + threadIdx.x;
    if (idx < 128 * 320) {
        int co = idx / 320, j = idx % 320;
        int kidx = 2 * j;
        int k = kidx >> 7, ci = kidx & 127;
        float v0 = conv_w[(co * 128 + ci) * 5 + k];
        float v1 = conv_w[(co * 128 + ci + 1) * 5 + k];
        unsigned uh, ul; split2(v0, v1, uh, ul);
        g_wp_hi[idx] = uh; g_wp_lo[idx] = ul;
    }
    if (idx < 128 * 64) {
        int g = idx / 64, j = idx % 64;
        float v0 = Wih1[g * 128 + 2 * j];
        float v1 = Wih1[g * 128 + 2 * j + 1];
        unsigned uh, ul; split2(v0, v1, uh, ul);
        g_w1p_hi[idx] = uh; g_w1p_lo[idx] = ul;
    }
}

// ---------------- Kernel 1: conv1d via bf16-split tensor-core GEMM ----------------
#define LOADA(s, AH, AL) do {                                                  \
    int base_ = (s) * 8 + tig;                                                 \
    _Pragma("unroll")                                                          \
    for (int mi = 0; mi < 2; ++mi) {                                           \
        int co_ = co_base0 + mi * 16;                                          \
        AH[mi][0] = g_wp_hi[co_ * 320 + base_];                                \
        AH[mi][1] = g_wp_hi[(co_ + 8) * 320 + base_];                          \
        AH[mi][2] = g_wp_hi[co_ * 320 + base_ + 4];                            \
        AH[mi][3] = g_wp_hi[(co_ + 8) * 320 + base_ + 4];                      \
        AL[mi][0] = g_wp_lo[co_ * 320 + base_];                                \
        AL[mi][1] = g_wp_lo[(co_ + 8) * 320 + base_];                          \
        AL[mi][2] = g_wp_lo[co_ * 320 + base_ + 4];                            \
        AL[mi][3] = g_wp_lo[(co_ + 8) * 320 + base_ + 4];                      \
    }                                                                          \
} while (0)

#define MMASTEP(s, AH, AL) do {                                                \
    int k5_ = (s) >> 3; int crow_ = ((s) & 7) * 8;                             \
    _Pragma("unroll")                                                          \
    for (int ni = 0; ni < 8; ++ni) {                                           \
        int r_ = (wn * 64 + ni * 8 + gid + k5_) * 68 + crow_ + tig;            \
        unsigned bh0 = sH[r_], bh1 = sH[r_ + 4];                               \
        unsigned bl0 = sL[r_], bl1 = sL[r_ + 4];                               \
        _Pragma("unroll")                                                      \
        for (int mi = 0; mi < 2; ++mi) {                                       \
            MMA_BF16(acc[mi][ni], AH[mi][0],AH[mi][1],AH[mi][2],AH[mi][3], bh0,bh1); \
            MMA_BF16(acc[mi][ni], AH[mi][0],AH[mi][1],AH[mi][2],AH[mi][3], bl0,bl1); \
            MMA_BF16(acc[mi][ni], AL[mi][0],AL[mi][1],AL[mi][2],AL[mi][3], bh0,bh1); \
        }                                                                      \
    }                                                                          \
} while (0)

__global__ void __launch_bounds__(256) conv_mma_kernel(const float* __restrict__ x,
                                                       const float* __restrict__ cb) {
    extern __shared__ unsigned sm[];
    unsigned* sH = sm;               // 136 rows * 68 words
    unsigned* sL = sm + 136 * 68;

    int tid  = threadIdx.x;
    int warp = tid >> 5, lane = tid & 31;
    int gid  = lane >> 2, tig = lane & 3;
    int wm   = warp & 3;     // co tile (4 x 32)
    int wn   = warp >> 2;    // l tile  (2 x 64)
    int l0   = blockIdx.x * 128;
    int b    = blockIdx.y;

    // conflict-free staging: lane -> (j = jb + lane>>2, cw = cwb + lane&3)
    // STS word = j*68 + cw -> bank = 4*(lane>>2) + (lane&3) : all 32 distinct.
    const float* xb = x + (size_t)b * XBSTR;
    for (int it = warp; it < 17 * 16; it += 8) {
        int jb  = (it >> 4) * 8;
        int cwb = (it & 15) * 4;
        int j  = jb + (lane >> 2);
        int cw = cwb + (lane & 3);
        int l  = l0 + j;
        int ci = cw * 2;
        float v0 = 0.0f, v1 = 0.0f;
        if (l < LIN) { v0 = xb[ci * LIN + l]; v1 = xb[(ci + 1) * LIN + l]; }
        unsigned uh, ul; split2(v0, v1, uh, ul);
        sH[j * 68 + cw] = uh;
        sL[j * 68 + cw] = ul;
    }
    __syncthreads();

    float acc[2][8][4];
    #pragma unroll
    for (int mi = 0; mi < 2; ++mi)
        #pragma unroll
        for (int ni = 0; ni < 8; ++ni)
            #pragma unroll
            for (int q = 0; q < 4; ++q) acc[mi][ni][q] = 0.0f;

    int co_base0 = wm * 32 + gid;

    // software-pipelined A over 40 k-slices (slice s: base uint = s*8+tig)
    unsigned A0h[2][4], A0l[2][4], A1h[2][4], A1l[2][4];
    LOADA(0, A0h, A0l);
    for (int s = 0; s < 40; s += 2) {
        LOADA(s + 1, A1h, A1l);
        MMASTEP(s, A0h, A0l);
        if (s + 2 < 40) LOADA(s + 2, A0h, A0l);
        MMASTEP(s + 1, A1h, A1l);
    }

    // epilogue: +bias, split to bf16 hi/lo, write flat conv layout
    __nv_bfloat16* oh = g_seq_hi + (size_t)b * CBSTR;
    __nv_bfloat16* ol = g_seq_lo + (size_t)b * CBSTR;
    #pragma unroll
    for (int mi = 0; mi < 2; ++mi) {
        int coA = co_base0 + mi * 16;
        int coB = coA + 8;
        float biasA = cb[coA], biasB = cb[coB];
        #pragma unroll
        for (int ni = 0; ni < 8; ++ni) {
            int lg = l0 + wn * 64 + ni * 8 + tig * 2;
            if (lg < LOUT) {
                unsigned uh, ul;
                int fA = coA * LOUT + lg;
                split2(acc[mi][ni][0] + biasA, acc[mi][ni][1] + biasA, uh, ul);
                *(unsigned*)(oh + fA) = uh; *(unsigned*)(ol + fA) = ul;
                int fB = coB * LOUT + lg;
                split2(acc[mi][ni][2] + biasB, acc[mi][ni][3] + biasB, uh, ul);
                *(unsigned*)(oh + fB) = uh; *(unsigned*)(ol + fB) = ul;
            }
        }
    }
}

// ---------------- Kernel 2: xg = seq @ Wih1^T + bias via bf16-split mma ----------------
__global__ void __launch_bounds__(256) xg_mma_kernel(const float* __restrict__ bih1,
                                                     const float* __restrict__ bhh1) {
    extern __shared__ unsigned sm[];
    unsigned* sH = sm;               // 128 rows * 68 words
    unsigned* sL = sm + 128 * 68;

    int tid  = threadIdx.x;
    int warp = tid >> 5, lane = tid & 31;
    int gid  = lane >> 2, tig = lane & 3;
    int wm   = warp & 3;     // t tile (4 x 32)
    int wn   = warp >> 2;    // gate tile (2 x 64)
    int t0   = blockIdx.x * 128;
    int b    = blockIdx.y;

    const __nv_bfloat16* shd = g_seq_hi + (size_t)b * CBSTR;
    const __nv_bfloat16* sld = g_seq_lo + (size_t)b * CBSTR;
    for (int row = warp; row < 128; row += 8) {
        int t = t0 + row;
        int d = lane * 4;
        uint2 vh = make_uint2(0u, 0u), vl = make_uint2(0u, 0u);
        if (t < TT) {
            vh = *(const uint2*)(shd + (size_t)t * D1 + d);
            vl = *(const uint2*)(sld + (size_t)t * D1 + d);
        }
        *(uint2*)((__nv_bfloat16*)sH + row * 136 + d) = vh;
        *(uint2*)((__nv_bfloat16*)sL + row * 136 + d) = vl;
    }
    __syncthreads();

    float acc[2][8][4];
    #pragma unroll
    for (int mi = 0; mi < 2; ++mi)
        #pragma unroll
        for (int ni = 0; ni < 8; ++ni)
            #pragma unroll
            for (int q = 0; q < 4; ++q) acc[mi][ni][q] = 0.0f;

    #pragma unroll
    for (int kk = 0; kk < 8; ++kk) {
        unsigned ah[2][4], al[2][4];
        #pragma unroll
        for (int mi = 0; mi < 2; ++mi) {
            int r = (wm * 32 + mi * 16 + gid) * 68 + kk * 8 + tig;
            ah[mi][0] = sH[r];           ah[mi][1] = sH[r + 8 * 68];
            ah[mi][2] = sH[r + 4];       ah[mi][3] = sH[r + 8 * 68 + 4];
            al[mi][0] = sL[r];           al[mi][1] = sL[r + 8 * 68];
            al[mi][2] = sL[r + 4];       al[mi][3] = sL[r + 8 * 68 + 4];
        }
        #pragma unroll
        for (int ni = 0; ni < 8; ++ni) {
            int gg = wn * 64 + ni * 8 + gid;
            unsigned bh0 = g_w1p_hi[gg * 64 + kk * 8 + tig];
            unsigned bh1 = g_w1p_hi[gg * 64 + kk * 8 + tig + 4];
            unsigned bl0 = g_w1p_lo[gg * 64 + kk * 8 + tig];
            unsigned bl1 = g_w1p_lo[gg * 64 + kk * 8 + tig + 4];
            #pragma unroll
            for (int mi = 0; mi < 2; ++mi) {
                MMA_BF16(acc[mi][ni], ah[mi][0], ah[mi][1], ah[mi][2], ah[mi][3], bh0, bh1);
                MMA_BF16(acc[mi][ni], ah[mi][0], ah[mi][1], ah[mi][2], ah[mi][3], bl0, bl1);
                MMA_BF16(acc[mi][ni], al[mi][0], al[mi][1], al[mi][2], al[mi][3], bh0, bh1);
            }
        }
    }

    float* xgb = g_xg + (size_t)b * CBSTR;
    #pragma unroll
    for (int ni = 0; ni < 8; ++ni) {
        int gcol = wn * 64 + ni * 8 + tig * 2;
        float bi0 = bih1[gcol] + bhh1[gcol];
        float bi1 = bih1[gcol + 1] + bhh1[gcol + 1];
        #pragma unroll
        for (int mi = 0; mi < 2; ++mi) {
            int tA = t0 + wm * 32 + mi * 16 + gid;
            if (tA < TT) {
                float2 v = make_float2(acc[mi][ni][0] + bi0, acc[mi][ni][1] + bi1);
                *(float2*)(xgb + (size_t)tA * D1 + gcol) = v;
            }
            int tB = tA + 8;
            if (tB < TT) {
                float2 v = make_float2(acc[mi][ni][2] + bi0, acc[mi][ni][3] + bi1);
                *(float2*)(xgb + (size_t)tB * D1 + gcol) = v;
            }
        }
    }
}

// ---------------- Kernel 3: 3-layer LSTM recurrence ----------------
// Gate remap: lane = 4*cell_local + gate_type -> a cell's 4 gates live in
// adjacent lanes of ONE warp. Activations per-lane (single sigmoid MUFU path;
// tanh = 2*sig(2x)-1), gathered via shfl_xor butterfly, cell state in regs.
// h buffers ping-pong; 3 barriers/step.
__global__ void __launch_bounds__(128) lstm_kernel(
    const float* __restrict__ Whh1,
    const float* __restrict__ Wih2, const float* __restrict__ Whh2,
    const float* __restrict__ bih2, const float* __restrict__ bhh2,
    const float* __restrict__ Wih3, const float* __restrict__ Whh3,
    const float* __restrict__ bih3, const float* __restrict__ bhh3,
    float* __restrict__ out)
{
    __shared__ float h1s[2][32], h2s[2][16], h3s[2][32];

    int tid = threadIdx.x, b = blockIdx.x;
    int warp = tid >> 5, lane = tid & 31;
    int cl = lane >> 2;          // local cell
    int gt = lane & 3;           // gate type: 0=i,1=f,2=g,3=o
    int cell13 = warp * 8 + cl;          // 0..31
    int gate13 = gt * 32 + cell13;       // PyTorch gate row (i|f|g|o blocks)
    bool hasL2 = (warp < 2);
    int cell2 = warp * 8 + cl;           // 0..15 when warp<2
    int gate2 = gt * 16 + cell2;

    // weights in registers (rows are contiguous in PyTorch layout)
    float4 w1[8], w3i[4], w3h[8];
    #pragma unroll
    for (int i = 0; i < 8; ++i) w1[i]  = *(const float4*)(Whh1 + gate13 * 32 + i * 4);
    #pragma unroll
    for (int i = 0; i < 4; ++i) w3i[i] = *(const float4*)(Wih3 + gate13 * 16 + i * 4);
    #pragma unroll
    for (int i = 0; i < 8; ++i) w3h[i] = *(const float4*)(Whh3 + gate13 * 32 + i * 4);
    float4 w2i[8], w2h[4];
    float bias2 = 0.0f;
    if (hasL2) {
        #pragma unroll
        for (int i = 0; i < 8; ++i) w2i[i] = *(const float4*)(Wih2 + gate2 * 32 + i * 4);
        #pragma unroll
        for (int i = 0; i < 4; ++i) w2h[i] = *(const float4*)(Whh2 + gate2 * 16 + i * 4);
        bias2 = bih2[gate2] + bhh2[gate2];
    }
    float bias3 = bih3[gate13] + bhh3[gate13];

    if (tid < 32) { h1s[0][tid] = 0.f; h3s[0][tid] = 0.f; }
    if (tid < 16) { h2s[0][tid] = 0.f; }
    float c1 = 0.f, c2 = 0.f, c3 = 0.f;
    __syncthreads();

    // activation unify: a = sig(pre*preMul)*postMul + postAdd  (tanh for gt==2)
    float preMul  = (gt == 2) ? 2.0f : 1.0f;
    float postAdd = (gt == 2) ? -1.0f : 0.0f;

    const float* xgp = g_xg + (size_t)b * CBSTR + gate13;
    float xnext = xgp[0];

    #define BUTTERFLY_CELL(pre, cstate, hv) do {                               \
        float s_ = sigf((pre) * preMul);                                       \
        float a_ = fmaf(s_, preMul, postAdd);                                  \
        float p1_ = __shfl_xor_sync(0xffffffffu, a_, 1);                       \
        float p2_ = __shfl_xor_sync(0xffffffffu, a_, 2);                       \
        float p3_ = __shfl_xor_sync(0xffffffffu, p1_, 2);                      \
        bool g1_ = gt & 1; bool g2_ = gt & 2;                                  \
        float s01  = g1_ ? p1_ : a_;                                           \
        float s01x = g1_ ? a_  : p1_;                                          \
        float s23  = g1_ ? p3_ : p2_;                                          \
        float s23x = g1_ ? p2_ : p3_;                                          \
        float ai = g2_ ? s23  : s01;                                           \
        float af = g2_ ? s23x : s01x;                                          \
        float ag = g2_ ? s01  : s23;                                           \
        float ao = g2_ ? s01x : s23x;                                          \
        cstate = af * cstate + ai * ag;                                        \
        hv = ao * tanhfast(cstate);                                            \
    } while (0)

    for (int t = 0; t < TT; ++t) {
        int p = t & 1, q = p ^ 1;
        float xcur = xnext;
        if (t + 1 < TT) xnext = xgp[(size_t)(t + 1) * D1];

        // ---- layer 1 ----
        {
            float a0 = xcur, a1 = 0.f, a2 = 0.f, a3 = 0.f;
            #pragma unroll
            for (int i = 0; i < 8; ++i) {
                float4 h = ((const float4*)h1s[p])[i];
                a0 = fmaf(h.x, w1[i].x, a0); a1 = fmaf(h.y, w1[i].y, a1);
                a2 = fmaf(h.z, w1[i].z, a2); a3 = fmaf(h.w, w1[i].w, a3);
            }
            float pre = (a0 + a1) + (a2 + a3);
            float hv;
            BUTTERFLY_CELL(pre, c1, hv);
            if (gt == 0) h1s[q][cell13] = hv;
        }
        __syncthreads();

        // ---- layer 2 (warps 0,1) ----
        if (hasL2) {
            float a0 = bias2, a1 = 0.f, a2 = 0.f, a3 = 0.f;
            #pragma unroll
            for (int i = 0; i < 8; ++i) {
                float4 h = ((const float4*)h1s[q])[i];
                a0 = fmaf(h.x, w2i[i].x, a0); a1 = fmaf(h.y, w2i[i].y, a1);
                a2 = fmaf(h.z, w2i[i].z, a2); a3 = fmaf(h.w, w2i[i].w, a3);
            }
            #pragma unroll
            for (int i = 0; i < 4; ++i) {
                float4 h = ((const float4*)h2s[p])[i];
                a0 = fmaf(h.x, w2h[i].x, a0); a1 = fmaf(h.y, w2h[i].y, a1);
                a2 = fmaf(h.z, w2h[i].z, a2); a3 = fmaf(h.w, w2h[i].w, a3);
            }
            float pre = (a0 + a1) + (a2 + a3);
            float hv;
            BUTTERFLY_CELL(pre, c2, hv);
            if (gt == 0) h2s[q][cell2] = hv;
        }
        __syncthreads();

        // ---- layer 3 ----
        {
            float a0 = bias3, a1 = 0.f, a2 = 0.f, a3 = 0.f;
            #pragma unroll
            for (int i = 0; i < 4; ++i) {
                float4 h = ((const float4*)h2s[q])[i];
                a0 = fmaf(h.x, w3i[i].x, a0); a1 = fmaf(h.y, w3i[i].y, a1);
                a2 = fmaf(h.z, w3i[i].z, a2); a3 = fmaf(h.w, w3i[i].w, a3);
            }
            #pragma unroll
            for (int i = 0; i < 8; ++i) {
                float4 h = ((const float4*)h3s[p])[i];
                a0 = fmaf(h.x, w3h[i].x, a0); a1 = fmaf(h.y, w3h[i].y, a1);
                a2 = fmaf(h.z, w3h[i].z, a2); a3 = fmaf(h.w, w3h[i].w, a3);
            }
            float pre = (a0 + a1) + (a2 + a3);
            float hv;
            BUTTERFLY_CELL(pre, c3, hv);
            if (gt == 0) h3s[q][cell13] = hv;
        }
        __syncthreads();
    }

    // last write went to buffer ((TT-1)&1)^1
    if (tid < 32) out[b * 32 + tid] = h3s[((TT - 1) & 1) ^ 1][tid];
}

// ---------------- launch ----------------
extern "C" void kernel_launch(void* const* d_in, const int* in_sizes, int n_in,
                              void* d_out, int out_size) {
    const float* x      = (const float*)d_in[0];
    const float* conv_w = (const float*)d_in[1];
    const float* conv_b = (const float*)d_in[2];
    const float* Wih1   = (const float*)d_in[3];
    const float* Whh1   = (const float*)d_in[4];
    const float* bih1   = (const float*)d_in[5];
    const float* bhh1   = (const float*)d_in[6];
    const float* Wih2   = (const float*)d_in[7];
    const float* Whh2   = (const float*)d_in[8];
    const float* bih2   = (const float*)d_in[9];
    const float* bhh2   = (const float*)d_in[10];
    const float* Wih3   = (const float*)d_in[11];
    const float* Whh3   = (const float*)d_in[12];
    const float* bih3   = (const float*)d_in[13];
    const float* bhh3   = (const float*)d_in[14];
    float* out = (float*)d_out;

    const int conv_smem = 2 * 136 * 68 * 4;   // 73984 B
    const int xg_smem   = 2 * 128 * 68 * 4;   // 69632 B
    cudaFuncSetAttribute(conv_mma_kernel, cudaFuncAttributeMaxDynamicSharedMemorySize, conv_smem);
    cudaFuncSetAttribute(xg_mma_kernel,   cudaFuncAttributeMaxDynamicSharedMemorySize, xg_smem);

    prep_kernel<<<160, 256>>>(conv_w, Wih1);
    conv_mma_kernel<<<dim3(8, B), 256, conv_smem>>>(x, conv_b);
    xg_mma_kernel<<<dim3(8, B), 256, xg_smem>>>(bih1, bhh1);
    lstm_kernel<<<B, 128>>>(Whh1, Wih2, Whh2, bih2, bhh2,
                            Wih3, Whh3, bih3, bhh3, out);
}

// round 9
// speedup vs baseline: 1.5984x; 1.2359x over previous
#include <cuda_runtime.h>
#include <cuda_bf16.h>
#include <cstdint>

// Problem dims
#define B     512
#define CIN   128
#define LIN   1024
#define KW    5
#define LOUT  1020
#define TT    1020
#define D1    128

#define XBSTR   (CIN*LIN)        // 131072
#define CBSTR   (CIN*LOUT)       // 130560 == TT*D1

// ---- scratch (device globals; no runtime allocation allowed) ----
__device__ __nv_bfloat16 g_seq_hi[(size_t)B * CBSTR];
__device__ __nv_bfloat16 g_seq_lo[(size_t)B * CBSTR];
__device__ float         g_xg   [(size_t)B * CBSTR];
__device__ unsigned      g_wp_hi[128 * 320];   // conv W pairs [co][kidx/2], kidx=k*128+ci
__device__ unsigned      g_wp_lo[128 * 320];
__device__ unsigned      g_w1p_hi[128 * 64];   // Wih1 pairs [gate][d/2]
__device__ unsigned      g_w1p_lo[128 * 64];

__device__ __forceinline__ float sigf(float x) {
    return __fdividef(1.0f, 1.0f + __expf(-x));
}
__device__ __forceinline__ float tanhfast(float x) {
    x = fminf(15.0f, fmaxf(-15.0f, x));
    float e = __expf(2.0f * x);
    return __fdividef(e - 1.0f, e + 1.0f);
}

__device__ __forceinline__ void split2(float v0, float v1, unsigned &uh, unsigned &ul) {
    __nv_bfloat16 h0 = __float2bfloat16_rn(v0);
    __nv_bfloat16 h1 = __float2bfloat16_rn(v1);
    float r0 = v0 - __bfloat162float(h0);
    float r1 = v1 - __bfloat162float(h1);
    __nv_bfloat162 ph; ph.x = h0; ph.y = h1;
    __nv_bfloat162 pl; pl.x = __float2bfloat16_rn(r0); pl.y = __float2bfloat16_rn(r1);
    uh = *(unsigned*)&ph;
    ul = *(unsigned*)&pl;
}

#define MMA_BF16(d, a0,a1,a2,a3, b0,b1)                                     \
    asm volatile("mma.sync.aligned.m16n8k16.row.col.f32.bf16.bf16.f32 "     \
        "{%0,%1,%2,%3},{%4,%5,%6,%7},{%8,%9},{%0,%1,%2,%3};"                \
        : "+f"(d[0]), "+f"(d[1]), "+f"(d[2]), "+f"(d[3])                    \
        : "r"(a0), "r"(a1), "r"(a2), "r"(a3), "r"(b0), "r"(b1))

// ---------------- Kernel 0: pack weights into mma fragment order ----------------
__global__ void prep_kernel(const float* __restrict__ conv_w, const float* __restrict__ Wih1) {
    int idx = blockIdx.x * 256 + threadIdx.x;
    if (idx < 128 * 320) {
        int co = idx / 320, j = idx % 320;
        int kidx = 2 * j;
        int k = kidx >> 7, ci = kidx & 127;
        float v0 = conv_w[(co * 128 + ci) * 5 + k];
        float v1 = conv_w[(co * 128 + ci + 1) * 5 + k];
        unsigned uh, ul; split2(v0, v1, uh, ul);
        g_wp_hi[idx] = uh; g_wp_lo[idx] = ul;
    }
    if (idx < 128 * 64) {
        int g = idx / 64, j = idx % 64;
        float v0 = Wih1[g * 128 + 2 * j];
        float v1 = Wih1[g * 128 + 2 * j + 1];
        unsigned uh, ul; split2(v0, v1, uh, ul);
        g_w1p_hi[idx] = uh; g_w1p_lo[idx] = ul;
    }
}

// ---------------- Kernel 1: conv1d via bf16-split tensor-core GEMM ----------------
#define LOADA(s, AH, AL) do {                                                  \
    int base_ = (s) * 8 + tig;                                                 \
    _Pragma("unroll")                                                          \
    for (int mi = 0; mi < 2; ++mi) {                                           \
        int co_ = co_base0 + mi * 16;                                          \
        AH[mi][0] = g_wp_hi[co_ * 320 + base_];                                \
        AH[mi][1] = g_wp_hi[(co_ + 8) * 320 + base_];                          \
        AH[mi][2] = g_wp_hi[co_ * 320 + base_ + 4];                            \
        AH[mi][3] = g_wp_hi[(co_ + 8) * 320 + base_ + 4];                      \
        AL[mi][0] = g_wp_lo[co_ * 320 + base_];                                \
        AL[mi][1] = g_wp_lo[(co_ + 8) * 320 + base_];                          \
        AL[mi][2] = g_wp_lo[co_ * 320 + base_ + 4];                            \
        AL[mi][3] = g_wp_lo[(co_ + 8) * 320 + base_ + 4];                      \
    }                                                                          \
} while (0)

#define MMASTEP(s, AH, AL) do {                                                \
    int k5_ = (s) >> 3; int crow_ = ((s) & 7) * 8;                             \
    _Pragma("unroll")                                                          \
    for (int ni = 0; ni < 8; ++ni) {                                           \
        int r_ = (wn * 64 + ni * 8 + gid + k5_) * 68 + crow_ + tig;            \
        unsigned bh0 = sH[r_], bh1 = sH[r_ + 4];                               \
        unsigned bl0 = sL[r_], bl1 = sL[r_ + 4];                               \
        _Pragma("unroll")                                                      \
        for (int mi = 0; mi < 2; ++mi) {                                       \
            MMA_BF16(acc[mi][ni], AH[mi][0],AH[mi][1],AH[mi][2],AH[mi][3], bh0,bh1); \
            MMA_BF16(acc[mi][ni], AH[mi][0],AH[mi][1],AH[mi][2],AH[mi][3], bl0,bl1); \
            MMA_BF16(acc[mi][ni], AL[mi][0],AL[mi][1],AL[mi][2],AL[mi][3], bh0,bh1); \
        }                                                                      \
    }                                                                          \
} while (0)

__global__ void __launch_bounds__(256) conv_mma_kernel(const float* __restrict__ x,
                                                       const float* __restrict__ cb) {
    extern __shared__ unsigned sm[];
    unsigned* sH = sm;               // 136 rows * 68 words
    unsigned* sL = sm + 136 * 68;

    int tid  = threadIdx.x;
    int warp = tid >> 5, lane = tid & 31;
    int gid  = lane >> 2, tig = lane & 3;
    int wm   = warp & 3;
    int wn   = warp >> 2;
    int l0   = blockIdx.x * 128;
    int b    = blockIdx.y;

    const float* xb = x + (size_t)b * XBSTR;
    for (int it = warp; it < 17 * 16; it += 8) {
        int jb  = (it >> 4) * 8;
        int cwb = (it & 15) * 4;
        int j  = jb + (lane >> 2);
        int cw = cwb + (lane & 3);
        int l  = l0 + j;
        int ci = cw * 2;
        float v0 = 0.0f, v1 = 0.0f;
        if (l < LIN) { v0 = xb[ci * LIN + l]; v1 = xb[(ci + 1) * LIN + l]; }
        unsigned uh, ul; split2(v0, v1, uh, ul);
        sH[j * 68 + cw] = uh;
        sL[j * 68 + cw] = ul;
    }
    __syncthreads();

    float acc[2][8][4];
    #pragma unroll
    for (int mi = 0; mi < 2; ++mi)
        #pragma unroll
        for (int ni = 0; ni < 8; ++ni)
            #pragma unroll
            for (int q = 0; q < 4; ++q) acc[mi][ni][q] = 0.0f;

    int co_base0 = wm * 32 + gid;

    unsigned A0h[2][4], A0l[2][4], A1h[2][4], A1l[2][4];
    LOADA(0, A0h, A0l);
    for (int s = 0; s < 40; s += 2) {
        LOADA(s + 1, A1h, A1l);
        MMASTEP(s, A0h, A0l);
        if (s + 2 < 40) LOADA(s + 2, A0h, A0l);
        MMASTEP(s + 1, A1h, A1l);
    }

    __nv_bfloat16* oh = g_seq_hi + (size_t)b * CBSTR;
    __nv_bfloat16* ol = g_seq_lo + (size_t)b * CBSTR;
    #pragma unroll
    for (int mi = 0; mi < 2; ++mi) {
        int coA = co_base0 + mi * 16;
        int coB = coA + 8;
        float biasA = cb[coA], biasB = cb[coB];
        #pragma unroll
        for (int ni = 0; ni < 8; ++ni) {
            int lg = l0 + wn * 64 + ni * 8 + tig * 2;
            if (lg < LOUT) {
                unsigned uh, ul;
                int fA = coA * LOUT + lg;
                split2(acc[mi][ni][0] + biasA, acc[mi][ni][1] + biasA, uh, ul);
                *(unsigned*)(oh + fA) = uh; *(unsigned*)(ol + fA) = ul;
                int fB = coB * LOUT + lg;
                split2(acc[mi][ni][2] + biasB, acc[mi][ni][3] + biasB, uh, ul);
                *(unsigned*)(oh + fB) = uh; *(unsigned*)(ol + fB) = ul;
            }
        }
    }
}

// ---------------- Kernel 2: xg = seq @ Wih1^T + bias via bf16-split mma ----------------
__global__ void __launch_bounds__(256) xg_mma_kernel(const float* __restrict__ bih1,
                                                     const float* __restrict__ bhh1) {
    extern __shared__ unsigned sm[];
    unsigned* sH = sm;               // 128 rows * 68 words
    unsigned* sL = sm + 128 * 68;

    int tid  = threadIdx.x;
    int warp = tid >> 5, lane = tid & 31;
    int gid  = lane >> 2, tig = lane & 3;
    int wm   = warp & 3;
    int wn   = warp >> 2;
    int t0   = blockIdx.x * 128;
    int b    = blockIdx.y;

    const __nv_bfloat16* shd = g_seq_hi + (size_t)b * CBSTR;
    const __nv_bfloat16* sld = g_seq_lo + (size_t)b * CBSTR;
    for (int row = warp; row < 128; row += 8) {
        int t = t0 + row;
        int d = lane * 4;
        uint2 vh = make_uint2(0u, 0u), vl = make_uint2(0u, 0u);
        if (t < TT) {
            vh = *(const uint2*)(shd + (size_t)t * D1 + d);
            vl = *(const uint2*)(sld + (size_t)t * D1 + d);
        }
        *(uint2*)((__nv_bfloat16*)sH + row * 136 + d) = vh;
        *(uint2*)((__nv_bfloat16*)sL + row * 136 + d) = vl;
    }
    __syncthreads();

    float acc[2][8][4];
    #pragma unroll
    for (int mi = 0; mi < 2; ++mi)
        #pragma unroll
        for (int ni = 0; ni < 8; ++ni)
            #pragma unroll
            for (int q = 0; q < 4; ++q) acc[mi][ni][q] = 0.0f;

    #pragma unroll
    for (int kk = 0; kk < 8; ++kk) {
        unsigned ah[2][4], al[2][4];
        #pragma unroll
        for (int mi = 0; mi < 2; ++mi) {
            int r = (wm * 32 + mi * 16 + gid) * 68 + kk * 8 + tig;
            ah[mi][0] = sH[r];           ah[mi][1] = sH[r + 8 * 68];
            ah[mi][2] = sH[r + 4];       ah[mi][3] = sH[r + 8 * 68 + 4];
            al[mi][0] = sL[r];           al[mi][1] = sL[r + 8 * 68];
            al[mi][2] = sL[r + 4];       al[mi][3] = sL[r + 8 * 68 + 4];
        }
        #pragma unroll
        for (int ni = 0; ni < 8; ++ni) {
            int gg = wn * 64 + ni * 8 + gid;
            unsigned bh0 = g_w1p_hi[gg * 64 + kk * 8 + tig];
            unsigned bh1 = g_w1p_hi[gg * 64 + kk * 8 + tig + 4];
            unsigned bl0 = g_w1p_lo[gg * 64 + kk * 8 + tig];
            unsigned bl1 = g_w1p_lo[gg * 64 + kk * 8 + tig + 4];
            #pragma unroll
            for (int mi = 0; mi < 2; ++mi) {
                MMA_BF16(acc[mi][ni], ah[mi][0], ah[mi][1], ah[mi][2], ah[mi][3], bh0, bh1);
                MMA_BF16(acc[mi][ni], ah[mi][0], ah[mi][1], ah[mi][2], ah[mi][3], bl0, bl1);
                MMA_BF16(acc[mi][ni], al[mi][0], al[mi][1], al[mi][2], al[mi][3], bh0, bh1);
            }
        }
    }

    float* xgb = g_xg + (size_t)b * CBSTR;
    #pragma unroll
    for (int ni = 0; ni < 8; ++ni) {
        int gcol = wn * 64 + ni * 8 + tig * 2;
        float bi0 = bih1[gcol] + bhh1[gcol];
        float bi1 = bih1[gcol + 1] + bhh1[gcol + 1];
        #pragma unroll
        for (int mi = 0; mi < 2; ++mi) {
            int tA = t0 + wm * 32 + mi * 16 + gid;
            if (tA < TT) {
                float2 v = make_float2(acc[mi][ni][0] + bi0, acc[mi][ni][1] + bi1);
                *(float2*)(xgb + (size_t)tA * D1 + gcol) = v;
            }
            int tB = tA + 8;
            if (tB < TT) {
                float2 v = make_float2(acc[mi][ni][2] + bi0, acc[mi][ni][3] + bi1);
                *(float2*)(xgb + (size_t)tB * D1 + gcol) = v;
            }
        }
    }
}

// ---------------- Kernel 3: pipelined 3-layer LSTM recurrence ----------------
// Tick τ: L1 computes t=τ, L2 computes t=τ-1, L3 computes t=τ-2, concurrently.
// All reads from buf[(τ-1)&1], all writes to buf[τ&1], ONE barrier per tick.
// Thread pair per cell: even lane = gates (i,g), odd lane = gates (f,o);
// one shfl_xor(1) passes sig(i)*tanh(g); odd lane holds c, writes h.
// 160 threads: [0,64) L1 (32 cells), [64,96) L2 (16 cells), [96,160) L3 (32 cells).
__global__ void __launch_bounds__(160, 3) lstm_kernel(
    const float* __restrict__ Whh1,
    const float* __restrict__ Wih2, const float* __restrict__ Whh2,
    const float* __restrict__ bih2, const float* __restrict__ bhh2,
    const float* __restrict__ Wih3, const float* __restrict__ Whh3,
    const float* __restrict__ bih3, const float* __restrict__ bhh3,
    float* __restrict__ out)
{
    __shared__ float h1s[2][32], h2s[2][16], h3s[2][32];

    int tid = threadIdx.x, b = blockIdx.x;
    bool isL1 = tid < 64;
    bool isL2 = (tid >= 64) & (tid < 96);
    int local = isL1 ? tid : (isL2 ? tid - 64 : tid - 96);
    int cell = local >> 1;
    int half = local & 1;              // 0: (i,g)   1: (f,o)
    int H = isL2 ? 16 : 32;
    int ga = half ? H + cell : cell;            // f : i
    int gb = half ? 3 * H + cell : 2 * H + cell; // o : g

    // weights in registers: up to 2 long (32-dim) + 2 short (16-dim) rows
    float4 wLa[8], wLb[8], wSa[4], wSb[4];
    float biasa = 0.f, biasb = 0.f;
    if (isL1) {
        #pragma unroll
        for (int i = 0; i < 8; ++i) {
            wLa[i] = *(const float4*)(Whh1 + ga * 32 + i * 4);
            wLb[i] = *(const float4*)(Whh1 + gb * 32 + i * 4);
        }
    } else if (isL2) {
        #pragma unroll
        for (int i = 0; i < 8; ++i) {
            wLa[i] = *(const float4*)(Wih2 + ga * 32 + i * 4);
            wLb[i] = *(const float4*)(Wih2 + gb * 32 + i * 4);
        }
        #pragma unroll
        for (int i = 0; i < 4; ++i) {
            wSa[i] = *(const float4*)(Whh2 + ga * 16 + i * 4);
            wSb[i] = *(const float4*)(Whh2 + gb * 16 + i * 4);
        }
        biasa = bih2[ga] + bhh2[ga];
        biasb = bih2[gb] + bhh2[gb];
    } else {
        #pragma unroll
        for (int i = 0; i < 8; ++i) {
            wLa[i] = *(const float4*)(Whh3 + ga * 32 + i * 4);
            wLb[i] = *(const float4*)(Whh3 + gb * 32 + i * 4);
        }
        #pragma unroll
        for (int i = 0; i < 4; ++i) {
            wSa[i] = *(const float4*)(Wih3 + ga * 16 + i * 4);
            wSb[i] = *(const float4*)(Wih3 + gb * 16 + i * 4);
        }
        biasa = bih3[ga] + bhh3[ga];
        biasb = bih3[gb] + bhh3[gb];
    }

    if (tid < 32) { h1s[0][tid] = 0.f; h1s[1][tid] = 0.f;
                    h3s[0][tid] = 0.f; h3s[1][tid] = 0.f; }
    if (tid < 16) { h2s[0][tid] = 0.f; h2s[1][tid] = 0.f; }
    float cst = 0.f;
    __syncthreads();

    const float* xgp = g_xg + (size_t)b * CBSTR;
    float xa = 0.f, xb = 0.f;
    if (isL1) { xa = xgp[ga]; xb = xgp[gb]; }

    // activation+combine: pa=(i|f) pre, pb=(g|o) pre
    #define COMBINE(pa, pb, dstbuf) do {                                       \
        float va_ = sigf(pa);                                                  \
        float vb_ = half ? sigf(pb) : tanhfast(pb);                            \
        float pay_ = va_ * vb_;                                                \
        float got_ = __shfl_xor_sync(0xffffffffu, pay_, 1);                    \
        if (half) {                                                            \
            cst = fmaf(va_, cst, got_);                                        \
            (dstbuf)[cell] = vb_ * tanhfast(cst);                              \
        }                                                                      \
    } while (0)

    for (int tau = 0; tau < TT + 2; ++tau) {
        int wp = tau & 1, rp = wp ^ 1;

        if (isL1) {
            if (tau < TT) {
                float a0 = xa, a1 = 0.f, b0 = xb, b1 = 0.f;
                #pragma unroll
                for (int i = 0; i < 8; ++i) {
                    float4 h = ((const float4*)h1s[rp])[i];
                    a0 = fmaf(h.x, wLa[i].x, a0); a1 = fmaf(h.y, wLa[i].y, a1);
                    a0 = fmaf(h.z, wLa[i].z, a0); a1 = fmaf(h.w, wLa[i].w, a1);
                    b0 = fmaf(h.x, wLb[i].x, b0); b1 = fmaf(h.y, wLb[i].y, b1);
                    b0 = fmaf(h.z, wLb[i].z, b0); b1 = fmaf(h.w, wLb[i].w, b1);
                }
                if (tau + 1 < TT) {
                    xa = xgp[(size_t)(tau + 1) * D1 + ga];
                    xb = xgp[(size_t)(tau + 1) * D1 + gb];
                }
                float pa = a0 + a1, pb = b0 + b1;
                COMBINE(pa, pb, h1s[wp]);
            }
        } else if (isL2) {
            if (tau >= 1 && tau <= TT) {
                float a0 = biasa, a1 = 0.f, b0 = biasb, b1 = 0.f;
                #pragma unroll
                for (int i = 0; i < 8; ++i) {
                    float4 h = ((const float4*)h1s[rp])[i];
                    a0 = fmaf(h.x, wLa[i].x, a0); a1 = fmaf(h.y, wLa[i].y, a1);
                    a0 = fmaf(h.z, wLa[i].z, a0); a1 = fmaf(h.w, wLa[i].w, a1);
                    b0 = fmaf(h.x, wLb[i].x, b0); b1 = fmaf(h.y, wLb[i].y, b1);
                    b0 = fmaf(h.z, wLb[i].z, b0); b1 = fmaf(h.w, wLb[i].w, b1);
                }
                #pragma unroll
                for (int i = 0; i < 4; ++i) {
                    float4 h = ((const float4*)h2s[rp])[i];
                    a0 = fmaf(h.x, wSa[i].x, a0); a1 = fmaf(h.y, wSa[i].y, a1);
                    a0 = fmaf(h.z, wSa[i].z, a0); a1 = fmaf(h.w, wSa[i].w, a1);
                    b0 = fmaf(h.x, wSb[i].x, b0); b1 = fmaf(h.y, wSb[i].y, b1);
                    b0 = fmaf(h.z, wSb[i].z, b0); b1 = fmaf(h.w, wSb[i].w, b1);
                }
                float pa = a0 + a1, pb = b0 + b1;
                COMBINE(pa, pb, h2s[wp]);
            }
        } else {
            if (tau >= 2) {
                float a0 = biasa, a1 = 0.f, b0 = biasb, b1 = 0.f;
                #pragma unroll
                for (int i = 0; i < 4; ++i) {
                    float4 h = ((const float4*)h2s[rp])[i];
                    a0 = fmaf(h.x, wSa[i].x, a0); a1 = fmaf(h.y, wSa[i].y, a1);
                    a0 = fmaf(h.z, wSa[i].z, a0); a1 = fmaf(h.w, wSa[i].w, a1);
                    b0 = fmaf(h.x, wSb[i].x, b0); b1 = fmaf(h.y, wSb[i].y, b1);
                    b0 = fmaf(h.z, wSb[i].z, b0); b1 = fmaf(h.w, wSb[i].w, b1);
                }
                #pragma unroll
                for (int i = 0; i < 8; ++i) {
                    float4 h = ((const float4*)h3s[rp])[i];
                    a0 = fmaf(h.x, wLa[i].x, a0); a1 = fmaf(h.y, wLa[i].y, a1);
                    a0 = fmaf(h.z, wLa[i].z, a0); a1 = fmaf(h.w, wLa[i].w, a1);
                    b0 = fmaf(h.x, wLb[i].x, b0); b1 = fmaf(h.y, wLb[i].y, b1);
                    b0 = fmaf(h.z, wLb[i].z, b0); b1 = fmaf(h.w, wLb[i].w, b1);
                }
                float pa = a0 + a1, pb = b0 + b1;
                COMBINE(pa, pb, h3s[wp]);
            }
        }
        __syncthreads();
    }

    // last L3 write at tau = TT+1 -> buffer (TT+1)&1
    if (tid < 32) out[b * 32 + tid] = h3s[(TT + 1) & 1][tid];
}

// ---------------- launch ----------------
extern "C" void kernel_launch(void* const* d_in, const int* in_sizes, int n_in,
                              void* d_out, int out_size) {
    const float* x      = (const float*)d_in[0];
    const float* conv_w = (const float*)d_in[1];
    const float* conv_b = (const float*)d_in[2];
    const float* Wih1   = (const float*)d_in[3];
    const float* Whh1   = (const float*)d_in[4];
    const float* bih1   = (const float*)d_in[5];
    const float* bhh1   = (const float*)d_in[6];
    const float* Wih2   = (const float*)d_in[7];
    const float* Whh2   = (const float*)d_in[8];
    const float* bih2   = (const float*)d_in[9];
    const float* bhh2   = (const float*)d_in[10];
    const float* Wih3   = (const float*)d_in[11];
    const float* Whh3   = (const float*)d_in[12];
    const float* bih3   = (const float*)d_in[13];
    const float* bhh3   = (const float*)d_in[14];
    float* out = (float*)d_out;

    const int conv_smem = 2 * 136 * 68 * 4;   // 73984 B
    const int xg_smem   = 2 * 128 * 68 * 4;   // 69632 B
    cudaFuncSetAttribute(conv_mma_kernel, cudaFuncAttributeMaxDynamicSharedMemorySize, conv_smem);
    cudaFuncSetAttribute(xg_mma_kernel,   cudaFuncAttributeMaxDynamicSharedMemorySize, xg_smem);

    prep_kernel<<<160, 256>>>(conv_w, Wih1);
    conv_mma_kernel<<<dim3(8, B), 256, conv_smem>>>(x, conv_b);
    xg_mma_kernel<<<dim3(8, B), 256, xg_smem>>>(bih1, bhh1);
    lstm_kernel<<<B, 160>>>(Whh1, Wih2, Whh2, bih2, bhh2,
                            Wih3, Whh3, bih3, bhh3, out);
}

// round 11
// speedup vs baseline: 2.2411x; 1.4020x over previous
#include <cuda_runtime.h>
#include <cuda_bf16.h>
#include <cstdint>

// Problem dims
#define B     512
#define CIN   128
#define LIN   1024
#define KW    5
#define LOUT  1020
#define TT    1020
#define D1    128

#define XBSTR   (CIN*LIN)        // 131072
#define CBSTR   (CIN*LOUT)       // 130560 == TT*D1

// ---- scratch (device globals; no runtime allocation allowed) ----
__device__ __nv_bfloat16 g_seq_hi[(size_t)B * CBSTR];
__device__ __nv_bfloat16 g_seq_lo[(size_t)B * CBSTR];
__device__ float         g_xg   [(size_t)B * CBSTR];
__device__ unsigned      g_wp_hi[128 * 320];   // conv W pairs [co][kidx/2]
__device__ unsigned      g_wp_lo[128 * 320];
__device__ unsigned      g_w1p_hi[128 * 64];   // Wih1 pairs [gate][d/2]
__device__ unsigned      g_w1p_lo[128 * 64];
// load-linear repacked fragments
__device__ unsigned      g_wpk_hi[4 * 40 * 32 * 8];   // [wm][slice][lane][8]
__device__ unsigned      g_wpk_lo[4 * 40 * 32 * 8];
__device__ unsigned      g_w1k_hi[2 * 8 * 8 * 64];    // [wn][kk][ni][lane*2+r]
__device__ unsigned      g_w1k_lo[2 * 8 * 8 * 64];

__device__ __forceinline__ float sigf(float x) {
    return __fdividef(1.0f, 1.0f + __expf(-x));
}
__device__ __forceinline__ float tanhfast(float x) {
    x = fminf(15.0f, fmaxf(-15.0f, x));
    float e = __expf(2.0f * x);
    return __fdividef(e - 1.0f, e + 1.0f);
}

__device__ __forceinline__ void split2(float v0, float v1, unsigned &uh, unsigned &ul) {
    __nv_bfloat16 h0 = __float2bfloat16_rn(v0);
    __nv_bfloat16 h1 = __float2bfloat16_rn(v1);
    float r0 = v0 - __bfloat162float(h0);
    float r1 = v1 - __bfloat162float(h1);
    __nv_bfloat162 ph; ph.x = h0; ph.y = h1;
    __nv_bfloat162 pl; pl.x = __float2bfloat16_rn(r0); pl.y = __float2bfloat16_rn(r1);
    uh = *(unsigned*)&ph;
    ul = *(unsigned*)&pl;
}

#define MMA_BF16(d, a0,a1,a2,a3, b0,b1)                                     \
    asm volatile("mma.sync.aligned.m16n8k16.row.col.f32.bf16.bf16.f32 "     \
        "{%0,%1,%2,%3},{%4,%5,%6,%7},{%8,%9},{%0,%1,%2,%3};"                \
        : "+f"(d[0]), "+f"(d[1]), "+f"(d[2]), "+f"(d[3])                    \
        : "r"(a0), "r"(a1), "r"(a2), "r"(a3), "r"(b0), "r"(b1))

// ---------------- Kernel 0: pack weights into mma fragment order ----------------
__global__ void prep_kernel(const float* __restrict__ conv_w, const float* __restrict__ Wih1) {
    int idx = blockIdx.x * 256 + threadIdx.x;
    if (idx < 128 * 320) {
        int co = idx / 320, j = idx % 320;
        int kidx = 2 * j;
        int k = kidx >> 7, ci = kidx & 127;
        float v0 = conv_w[(co * 128 + ci) * 5 + k];
        float v1 = conv_w[(co * 128 + ci + 1) * 5 + k];
        unsigned uh, ul; split2(v0, v1, uh, ul);
        g_wp_hi[idx] = uh; g_wp_lo[idx] = ul;
    }
    if (idx < 128 * 64) {
        int g = idx / 64, j = idx % 64;
        float v0 = Wih1[g * 128 + 2 * j];
        float v1 = Wih1[g * 128 + 2 * j + 1];
        unsigned uh, ul; split2(v0, v1, uh, ul);
        g_w1p_hi[idx] = uh; g_w1p_lo[idx] = ul;
    }
}

// ---------------- Kernel 0b: repack into load-linear fragment order ----------------
__global__ void repack_kernel() {
    int idx = blockIdx.x * 256 + threadIdx.x;
    if (idx < 4 * 40 * 32 * 8) {
        // idx = ((wm*40+s)*32+lane)*8 + q ; q = mi*4 + j
        int q    = idx & 7;
        int lane = (idx >> 3) & 31;
        int s    = (idx >> 8) % 40;
        int wm   = idx / (40 * 256);
        int gid = lane >> 2, tig = lane & 3;
        int co = wm * 32 + gid + ((q >> 2) & 1) * 16 + (q & 1) * 8;
        int bw = s * 8 + tig + ((q >> 1) & 1) * 4;
        g_wpk_hi[idx] = g_wp_hi[co * 320 + bw];
        g_wpk_lo[idx] = g_wp_lo[co * 320 + bw];
    }
    if (idx < 2 * 8 * 8 * 64) {
        // idx = ((wn*8+kk)*8+ni)*64 + lane*2 + r
        int r    = idx & 1;
        int lane = (idx >> 1) & 31;
        int ni   = (idx >> 6) & 7;
        int kk   = (idx >> 9) & 7;
        int wn   = idx >> 12;
        int gid = lane >> 2, tig = lane & 3;
        int gg = wn * 64 + ni * 8 + gid;
        g_w1k_hi[idx] = g_w1p_hi[gg * 64 + kk * 8 + tig + r * 4];
        g_w1k_lo[idx] = g_w1p_lo[gg * 64 + kk * 8 + tig + r * 4];
    }
}

// ---------------- Kernel 1: conv1d via bf16-split tensor-core GEMM ----------------
#define LOADA(s, AH, AL) do {                                                  \
    const uint4* ph_ = (const uint4*)&g_wpk_hi[((wm * 40 + (s)) * 32 + lane) * 8]; \
    *(uint4*)&AH[0][0] = ph_[0];                                               \
    *(uint4*)&AH[1][0] = ph_[1];                                               \
    const uint4* pl_ = (const uint4*)&g_wpk_lo[((wm * 40 + (s)) * 32 + lane) * 8]; \
    *(uint4*)&AL[0][0] = pl_[0];                                               \
    *(uint4*)&AL[1][0] = pl_[1];                                               \
} while (0)

#define MMASTEP(s, AH, AL) do {                                                \
    int k5_ = (s) >> 3; int crow_ = ((s) & 7) * 8;                             \
    _Pragma("unroll")                                                          \
    for (int ni = 0; ni < 8; ++ni) {                                           \
        int r_ = (wn * 64 + ni * 8 + gid + k5_) * 68 + crow_ + tig;            \
        unsigned bh0 = sH[r_], bh1 = sH[r_ + 4];                               \
        unsigned bl0 = sL[r_], bl1 = sL[r_ + 4];                               \
        _Pragma("unroll")                                                      \
        for (int mi = 0; mi < 2; ++mi) {                                       \
            MMA_BF16(acc[mi][ni], AH[mi][0],AH[mi][1],AH[mi][2],AH[mi][3], bh0,bh1); \
            MMA_BF16(acc[mi][ni], AH[mi][0],AH[mi][1],AH[mi][2],AH[mi][3], bl0,bl1); \
            MMA_BF16(acc[mi][ni], AL[mi][0],AL[mi][1],AL[mi][2],AL[mi][3], bh0,bh1); \
        }                                                                      \
    }                                                                          \
} while (0)

__global__ void __launch_bounds__(256) conv_mma_kernel(const float* __restrict__ x,
                                                       const float* __restrict__ cb) {
    extern __shared__ unsigned sm[];
    unsigned* sH = sm;               // 136 rows * 68 words
    unsigned* sL = sm + 136 * 68;

    int tid  = threadIdx.x;
    int warp = tid >> 5, lane = tid & 31;
    int gid  = lane >> 2, tig = lane & 3;
    int wm   = warp & 3;
    int wn   = warp >> 2;
    int l0   = blockIdx.x * 128;
    int b    = blockIdx.y;

    const float* xb = x + (size_t)b * XBSTR;
    for (int it = warp; it < 17 * 16; it += 8) {
        int jb  = (it >> 4) * 8;
        int cwb = (it & 15) * 4;
        int j  = jb + (lane >> 2);
        int cw = cwb + (lane & 3);
        int l  = l0 + j;
        int ci = cw * 2;
        float v0 = 0.0f, v1 = 0.0f;
        if (l < LIN) { v0 = xb[ci * LIN + l]; v1 = xb[(ci + 1) * LIN + l]; }
        unsigned uh, ul; split2(v0, v1, uh, ul);
        sH[j * 68 + cw] = uh;
        sL[j * 68 + cw] = ul;
    }
    __syncthreads();

    float acc[2][8][4];
    #pragma unroll
    for (int mi = 0; mi < 2; ++mi)
        #pragma unroll
        for (int ni = 0; ni < 8; ++ni)
            #pragma unroll
            for (int q = 0; q < 4; ++q) acc[mi][ni][q] = 0.0f;

    unsigned A0h[2][4], A0l[2][4], A1h[2][4], A1l[2][4];
    LOADA(0, A0h, A0l);
    for (int s = 0; s < 40; s += 2) {
        LOADA(s + 1, A1h, A1l);
        MMASTEP(s, A0h, A0l);
        if (s + 2 < 40) LOADA(s + 2, A0h, A0l);
        MMASTEP(s + 1, A1h, A1l);
    }

    int co_base0 = wm * 32 + gid;
    __nv_bfloat16* oh = g_seq_hi + (size_t)b * CBSTR;
    __nv_bfloat16* ol = g_seq_lo + (size_t)b * CBSTR;
    #pragma unroll
    for (int mi = 0; mi < 2; ++mi) {
        int coA = co_base0 + mi * 16;
        int coB = coA + 8;
        float biasA = cb[coA], biasB = cb[coB];
        #pragma unroll
        for (int ni = 0; ni < 8; ++ni) {
            int lg = l0 + wn * 64 + ni * 8 + tig * 2;
            if (lg < LOUT) {
                unsigned uh, ul;
                int fA = coA * LOUT + lg;
                split2(acc[mi][ni][0] + biasA, acc[mi][ni][1] + biasA, uh, ul);
                *(unsigned*)(oh + fA) = uh; *(unsigned*)(ol + fA) = ul;
                int fB = coB * LOUT + lg;
                split2(acc[mi][ni][2] + biasB, acc[mi][ni][3] + biasB, uh, ul);
                *(unsigned*)(oh + fB) = uh; *(unsigned*)(ol + fB) = ul;
            }
        }
    }
}

// ---------------- Kernel 2: xg = seq @ Wih1^T + bias via bf16-split mma ----------------
__global__ void __launch_bounds__(256) xg_mma_kernel(const float* __restrict__ bih1,
                                                     const float* __restrict__ bhh1) {
    extern __shared__ unsigned sm[];
    unsigned* sH = sm;               // 128 rows * 68 words
    unsigned* sL = sm + 128 * 68;

    int tid  = threadIdx.x;
    int warp = tid >> 5, lane = tid & 31;
    int gid  = lane >> 2, tig = lane & 3;
    int wm   = warp & 3;
    int wn   = warp >> 2;
    int t0   = blockIdx.x * 128;
    int b    = blockIdx.y;

    const __nv_bfloat16* shd = g_seq_hi + (size_t)b * CBSTR;
    const __nv_bfloat16* sld = g_seq_lo + (size_t)b * CBSTR;
    for (int row = warp; row < 128; row += 8) {
        int t = t0 + row;
        int d = lane * 4;
        uint2 vh = make_uint2(0u, 0u), vl = make_uint2(0u, 0u);
        if (t < TT) {
            vh = *(const uint2*)(shd + (size_t)t * D1 + d);
            vl = *(const uint2*)(sld + (size_t)t * D1 + d);
        }
        *(uint2*)((__nv_bfloat16*)sH + row * 136 + d) = vh;
        *(uint2*)((__nv_bfloat16*)sL + row * 136 + d) = vl;
    }
    __syncthreads();

    float acc[2][8][4];
    #pragma unroll
    for (int mi = 0; mi < 2; ++mi)
        #pragma unroll
        for (int ni = 0; ni < 8; ++ni)
            #pragma unroll
            for (int q = 0; q < 4; ++q) acc[mi][ni][q] = 0.0f;

    #pragma unroll
    for (int kk = 0; kk < 8; ++kk) {
        unsigned ah[2][4], al[2][4];
        #pragma unroll
        for (int mi = 0; mi < 2; ++mi) {
            int r = (wm * 32 + mi * 16 + gid) * 68 + kk * 8 + tig;
            ah[mi][0] = sH[r];           ah[mi][1] = sH[r + 8 * 68];
            ah[mi][2] = sH[r + 4];       ah[mi][3] = sH[r + 8 * 68 + 4];
            al[mi][0] = sL[r];           al[mi][1] = sL[r + 8 * 68];
            al[mi][2] = sL[r + 4];       al[mi][3] = sL[r + 8 * 68 + 4];
        }
        #pragma unroll
        for (int ni = 0; ni < 8; ++ni) {
            int wi = ((wn * 8 + kk) * 8 + ni) * 64 + lane * 2;
            uint2 wh = *(const uint2*)&g_w1k_hi[wi];
            uint2 wl = *(const uint2*)&g_w1k_lo[wi];
            unsigned bh0 = wh.x, bh1 = wh.y;
            unsigned bl0 = wl.x, bl1 = wl.y;
            #pragma unroll
            for (int mi = 0; mi < 2; ++mi) {
                MMA_BF16(acc[mi][ni], ah[mi][0], ah[mi][1], ah[mi][2], ah[mi][3], bh0, bh1);
                MMA_BF16(acc[mi][ni], ah[mi][0], ah[mi][1], ah[mi][2], ah[mi][3], bl0, bl1);
                MMA_BF16(acc[mi][ni], al[mi][0], al[mi][1], al[mi][2], al[mi][3], bh0, bh1);
            }
        }
    }

    float* xgb = g_xg + (size_t)b * CBSTR;
    #pragma unroll
    for (int ni = 0; ni < 8; ++ni) {
        int gcol = wn * 64 + ni * 8 + tig * 2;
        float bi0 = bih1[gcol] + bhh1[gcol];
        float bi1 = bih1[gcol + 1] + bhh1[gcol + 1];
        #pragma unroll
        for (int mi = 0; mi < 2; ++mi) {
            int tA = t0 + wm * 32 + mi * 16 + gid;
            if (tA < TT) {
                float2 v = make_float2(acc[mi][ni][0] + bi0, acc[mi][ni][1] + bi1);
                *(float2*)(xgb + (size_t)tA * D1 + gcol) = v;
            }
            int tB = tA + 8;
            if (tB < TT) {
                float2 v = make_float2(acc[mi][ni][2] + bi0, acc[mi][ni][3] + bi1);
                *(float2*)(xgb + (size_t)tB * D1 + gcol) = v;
            }
        }
    }
}

// ---------------- Kernel 3: pipelined 3-layer LSTM, 2 batches per CTA ----------------
// Tick τ: L1 computes t=τ, L2 t=τ-1, L3 t=τ-2, concurrently; one barrier/tick.
// Each CTA handles batches 2*bid and 2*bid+1 — weights (register-resident) are
// shared, per-thread FMA doubles, amortizing barrier/shuffle/MUFU overhead.
__global__ void __launch_bounds__(160, 2) lstm_kernel(
    const float* __restrict__ Whh1,
    const float* __restrict__ Wih2, const float* __restrict__ Whh2,
    const float* __restrict__ bih2, const float* __restrict__ bhh2,
    const float* __restrict__ Wih3, const float* __restrict__ Whh3,
    const float* __restrict__ bih3, const float* __restrict__ bhh3,
    float* __restrict__ out)
{
    __shared__ float h1s[2][2][32], h2s[2][2][16], h3s[2][2][32]; // [batch][phase][cell]

    int tid = threadIdx.x;
    int bb = blockIdx.x * 2;
    bool isL1 = tid < 64;
    bool isL2 = (tid >= 64) & (tid < 96);
    int local = isL1 ? tid : (isL2 ? tid - 64 : tid - 96);
    int cell = local >> 1;
    int half = local & 1;              // 0: (i,g)   1: (f,o)
    int H = isL2 ? 16 : 32;
    int ga = half ? H + cell : cell;
    int gb = half ? 3 * H + cell : 2 * H + cell;

    float4 wLa[8], wLb[8], wSa[4], wSb[4];
    float biasa = 0.f, biasb = 0.f;
    if (isL1) {
        #pragma unroll
        for (int i = 0; i < 8; ++i) {
            wLa[i] = *(const float4*)(Whh1 + ga * 32 + i * 4);
            wLb[i] = *(const float4*)(Whh1 + gb * 32 + i * 4);
        }
    } else if (isL2) {
        #pragma unroll
        for (int i = 0; i < 8; ++i) {
            wLa[i] = *(const float4*)(Wih2 + ga * 32 + i * 4);
            wLb[i] = *(const float4*)(Wih2 + gb * 32 + i * 4);
        }
        #pragma unroll
        for (int i = 0; i < 4; ++i) {
            wSa[i] = *(const float4*)(Whh2 + ga * 16 + i * 4);
            wSb[i] = *(const float4*)(Whh2 + gb * 16 + i * 4);
        }
        biasa = bih2[ga] + bhh2[ga];
        biasb = bih2[gb] + bhh2[gb];
    } else {
        #pragma unroll
        for (int i = 0; i < 8; ++i) {
            wLa[i] = *(const float4*)(Whh3 + ga * 32 + i * 4);
            wLb[i] = *(const float4*)(Whh3 + gb * 32 + i * 4);
        }
        #pragma unroll
        for (int i = 0; i < 4; ++i) {
            wSa[i] = *(const float4*)(Wih3 + ga * 16 + i * 4);
            wSb[i] = *(const float4*)(Wih3 + gb * 16 + i * 4);
        }
        biasa = bih3[ga] + bhh3[ga];
        biasb = bih3[gb] + bhh3[gb];
    }

    if (tid < 32) {
        h1s[0][0][tid] = 0.f; h1s[0][1][tid] = 0.f;
        h1s[1][0][tid] = 0.f; h1s[1][1][tid] = 0.f;
        h3s[0][0][tid] = 0.f; h3s[0][1][tid] = 0.f;
        h3s[1][0][tid] = 0.f; h3s[1][1][tid] = 0.f;
    }
    if (tid < 16) {
        h2s[0][0][tid] = 0.f; h2s[0][1][tid] = 0.f;
        h2s[1][0][tid] = 0.f; h2s[1][1][tid] = 0.f;
    }
    float cst0 = 0.f, cst1 = 0.f;
    __syncthreads();

    const float* xg0 = g_xg + (size_t)bb * CBSTR;
    const float* xg1 = g_xg + (size_t)(bb + 1) * CBSTR;
    float xa0 = 0.f, xb0 = 0.f, xa1 = 0.f, xb1 = 0.f;
    if (isL1) { xa0 = xg0[ga]; xb0 = xg0[gb]; xa1 = xg1[ga]; xb1 = xg1[gb]; }

    #define COMBINE2(pa0, pb0, pa1, pb1, d0, d1) do {                          \
        float va0_ = sigf(pa0);                                                \
        float va1_ = sigf(pa1);                                                \
        float vb0_ = half ? sigf(pb0) : tanhfast(pb0);                         \
        float vb1_ = half ? sigf(pb1) : tanhfast(pb1);                         \
        float pay0_ = va0_ * vb0_;                                             \
        float pay1_ = va1_ * vb1_;                                             \
        float got0_ = __shfl_xor_sync(0xffffffffu, pay0_, 1);                  \
        float got1_ = __shfl_xor_sync(0xffffffffu, pay1_, 1);                  \
        if (half) {                                                            \
            cst0 = fmaf(va0_, cst0, got0_);                                    \
            cst1 = fmaf(va1_, cst1, got1_);                                    \
            (d0)[cell] = vb0_ * tanhfast(cst0);                                \
            (d1)[cell] = vb1_ * tanhfast(cst1);                                \
        }                                                                      \
    } while (0)

    #define GEMV_L(buf0, buf1, A00, A01, B00, B01, A10, A11, B10, B11) do {    \
        _Pragma("unroll")                                                      \
        for (int i = 0; i < 8; ++i) {                                          \
            float4 h0 = ((const float4*)(buf0))[i];                            \
            float4 h1 = ((const float4*)(buf1))[i];                            \
            A00 = fmaf(h0.x, wLa[i].x, A00); A01 = fmaf(h0.y, wLa[i].y, A01);  \
            A00 = fmaf(h0.z, wLa[i].z, A00); A01 = fmaf(h0.w, wLa[i].w, A01);  \
            B00 = fmaf(h0.x, wLb[i].x, B00); B01 = fmaf(h0.y, wLb[i].y, B01);  \
            B00 = fmaf(h0.z, wLb[i].z, B00); B01 = fmaf(h0.w, wLb[i].w, B01);  \
            A10 = fmaf(h1.x, wLa[i].x, A10); A11 = fmaf(h1.y, wLa[i].y, A11);  \
            A10 = fmaf(h1.z, wLa[i].z, A10); A11 = fmaf(h1.w, wLa[i].w, A11);  \
            B10 = fmaf(h1.x, wLb[i].x, B10); B11 = fmaf(h1.y, wLb[i].y, B11);  \
            B10 = fmaf(h1.z, wLb[i].z, B10); B11 = fmaf(h1.w, wLb[i].w, B11);  \
        }                                                                      \
    } while (0)

    #define GEMV_S(buf0, buf1, A00, A01, B00, B01, A10, A11, B10, B11) do {    \
        _Pragma("unroll")                                                      \
        for (int i = 0; i < 4; ++i) {                                          \
            float4 h0 = ((const float4*)(buf0))[i];                            \
            float4 h1 = ((const float4*)(buf1))[i];                            \
            A00 = fmaf(h0.x, wSa[i].x, A00); A01 = fmaf(h0.y, wSa[i].y, A01);  \
            A00 = fmaf(h0.z, wSa[i].z, A00); A01 = fmaf(h0.w, wSa[i].w, A01);  \
            B00 = fmaf(h0.x, wSb[i].x, B00); B01 = fmaf(h0.y, wSb[i].y, B01);  \
            B00 = fmaf(h0.z, wSb[i].z, B00); B01 = fmaf(h0.w, wSb[i].w, B01);  \
            A10 = fmaf(h1.x, wSa[i].x, A10); A11 = fmaf(h1.y, wSa[i].y, A11);  \
            A10 = fmaf(h1.z, wSa[i].z, A10); A11 = fmaf(h1.w, wSa[i].w, A11);  \
            B10 = fmaf(h1.x, wSb[i].x, B10); B11 = fmaf(h1.y, wSb[i].y, B11);  \
            B10 = fmaf(h1.z, wSb[i].z, B10); B11 = fmaf(h1.w, wSb[i].w, B11);  \
        }                                                                      \
    } while (0)

    for (int tau = 0; tau < TT + 2; ++tau) {
        int wp = tau & 1, rp = wp ^ 1;

        if (isL1) {
            if (tau < TT) {
                float a00 = xa0, a01 = 0.f, b00 = xb0, b01 = 0.f;
                float a10 = xa1, a11 = 0.f, b10 = xb1, b11 = 0.f;
                GEMV_L(h1s[0][rp], h1s[1][rp], a00, a01, b00, b01, a10, a11, b10, b11);
                if (tau + 1 < TT) {
                    size_t off = (size_t)(tau + 1) * D1;
                    xa0 = xg0[off + ga]; xb0 = xg0[off + gb];
                    xa1 = xg1[off + ga]; xb1 = xg1[off + gb];
                }
                COMBINE2(a00 + a01, b00 + b01, a10 + a11, b10 + b11,
                         h1s[0][wp], h1s[1][wp]);
            }
        } else if (isL2) {
            if (tau >= 1 && tau <= TT) {
                float a00 = biasa, a01 = 0.f, b00 = biasb, b01 = 0.f;
                float a10 = biasa, a11 = 0.f, b10 = biasb, b11 = 0.f;
                GEMV_L(h1s[0][rp], h1s[1][rp], a00, a01, b00, b01, a10, a11, b10, b11);
                GEMV_S(h2s[0][rp], h2s[1][rp], a00, a01, b00, b01, a10, a11, b10, b11);
                COMBINE2(a00 + a01, b00 + b01, a10 + a11, b10 + b11,
                         h2s[0][wp], h2s[1][wp]);
            }
        } else {
            if (tau >= 2) {
                float a00 = biasa, a01 = 0.f, b00 = biasb, b01 = 0.f;
                float a10 = biasa, a11 = 0.f, b10 = biasb, b11 = 0.f;
                GEMV_S(h2s[0][rp], h2s[1][rp], a00, a01, b00, b01, a10, a11, b10, b11);
                GEMV_L(h3s[0][rp], h3s[1][rp], a00, a01, b00, b01, a10, a11, b10, b11);
                COMBINE2(a00 + a01, b00 + b01, a10 + a11, b10 + b11,
                         h3s[0][wp], h3s[1][wp]);
            }
        }
        __syncthreads();
    }

    if (tid < 32) {
        int fp = (TT + 1) & 1;
        out[bb * 32 + tid]       = h3s[0][fp][tid];
        out[(bb + 1) * 32 + tid] = h3s[1][fp][tid];
    }
}

// ---------------- launch ----------------
extern "C" void kernel_launch(void* const* d_in, const int* in_sizes, int n_in,
                              void* d_out, int out_size) {
    const float* x      = (const float*)d_in[0];
    const float* conv_w = (const float*)d_in[1];
    const float* conv_b = (const float*)d_in[2];
    const float* Wih1   = (const float*)d_in[3];
    const float* Whh1   = (const float*)d_in[4];
    const float* bih1   = (const float*)d_in[5];
    const float* bhh1   = (const float*)d_in[6];
    const float* Wih2   = (const float*)d_in[7];
    const float* Whh2   = (const float*)d_in[8];
    const float* bih2   = (const float*)d_in[9];
    const float* bhh2   = (const float*)d_in[10];
    const float* Wih3   = (const float*)d_in[11];
    const float* Whh3   = (const float*)d_in[12];
    const float* bih3   = (const float*)d_in[13];
    const float* bhh3   = (const float*)d_in[14];
    float* out = (float*)d_out;

    const int conv_smem = 2 * 136 * 68 * 4;   // 73984 B
    const int xg_smem   = 2 * 128 * 68 * 4;   // 69632 B
    cudaFuncSetAttribute(conv_mma_kernel, cudaFuncAttributeMaxDynamicSharedMemorySize, conv_smem);
    cudaFuncSetAttribute(xg_mma_kernel,   cudaFuncAttributeMaxDynamicSharedMemorySize, xg_smem);

    prep_kernel<<<160, 256>>>(conv_w, Wih1);
    repack_kernel<<<160, 256>>>();
    conv_mma_kernel<<<dim3(8, B), 256, conv_smem>>>(x, conv_b);
    xg_mma_kernel<<<dim3(8, B), 256, xg_smem>>>(bih1, bhh1);
    lstm_kernel<<<B / 2, 160>>>(Whh1, Wih2, Whh2, bih2, bhh2,
                                Wih3, Whh3, bih3, bhh3, out);
}